// round 3
// baseline (speedup 1.0000x reference)
#include <cuda_runtime.h>
#include <math.h>

#define Bn 64
#define Tn 800
#define Un 64
#define Nn 64
#define Kn 10
#define Hn 512
#define On 121
#define G4H 2048
#define HB (Hn*Bn)      /* 32768 */
#define NB (Nn*Bn)      /* 4096  */
#define ZB (G4H*Bn)     /* 131072 */
#define NCTA 128
#define NTHR 256

// Eigen/XLA-CPU pexp clamps its argument at ln(2^-126); replicate so the
// underflow tail ties bit-exactly (argmax -> 0) like the reference.
#define EXP_LO (-87.33654f)

// ---------------- device scratch (static, no allocations) ----------------
__device__ float g_h0[Tn*HB];              // [t][d][b]
__device__ float g_h1[Tn*HB];
__device__ float g_h2[Tn*HB];
__device__ float g_w [Tn*NB];              // [t][n][b]
__device__ float g_xz[Tn*ZB];              // [t][col][b]  (reused L1 then L2)
__device__ float g_c0[HB];
__device__ float g_c1[HB];
__device__ float g_c2[HB];
__device__ float g_kappa[Kn*Bn];           // [k][b]
__device__ unsigned g_barc[4];
__device__ unsigned g_barg[4];

// ---------------- grid barrier (all CTAs of one launch) ------------------
__device__ __forceinline__ void gridbar(int slot, unsigned* lg) {
    __threadfence();
    __syncthreads();
    if (threadIdx.x == 0) {
        unsigned target = ++(*lg);
        unsigned a = atomicAdd(&g_barc[slot], 1u);
        if (a == gridDim.x - 1) {
            g_barc[slot] = 0u;
            __threadfence();
            atomicExch(&g_barg[slot], target);
        } else {
            while (*((volatile unsigned*)&g_barg[slot]) < target) {
                __nanosleep(64);
            }
        }
    }
    __syncthreads();
}

__device__ __forceinline__ float sigf(float x) { return 1.f / (1.f + expf(-x)); }

// ---------------- init: zero states + barrier vars -----------------------
__global__ void k_init() {
    int i = blockIdx.x * blockDim.x + threadIdx.x;
    int stride = gridDim.x * blockDim.x;
    for (int j = i; j < HB; j += stride) { g_c0[j] = 0.f; g_c1[j] = 0.f; g_c2[j] = 0.f; }
    for (int j = i; j < Kn*Bn; j += stride) g_kappa[j] = 0.f;
    if (i < 4) { g_barc[i] = 0u; g_barg[i] = 0u; }
}

// =========================================================================
// Layer-0 scan + attention.  128 CTAs x 256 thr, persistent.
// CTA bx owns units u0=4*bx..+3 (16 gate columns).  Thread: cl=tid&15 (col),
// bg=tid>>4 (4-batch group).  Feature vector v[579] = [h(512), w(64), x(3)].
// =========================================================================
__global__ void __launch_bounds__(NTHR, 1)
k_scan0(const float* __restrict__ strokes, const float* __restrict__ trans,
        const float* __restrict__ W0, const float* __restrict__ R0,
        const float* __restrict__ b0, const float* __restrict__ Wd,
        const float* __restrict__ bd, float* __restrict__ attOut)
{
    extern __shared__ float sm[];
    float* sW  = sm;                 // 579*16
    float* sIn = sm + 579*16;        // 128*64
    __shared__ float sZ[16*64];
    __shared__ float sb[16];
    __shared__ float sPart[8*32];
    __shared__ float sy[32];
    __shared__ float skap[16];
    __shared__ float swf[72];

    const int tid = threadIdx.x;
    const int u0  = blockIdx.x * 4;
    const int cl  = tid & 15;
    const int bg  = tid >> 4;

    // stage weights once (rows: 0..511 R0, 512..575 W0[3..66], 576..578 W0[0..2])
    for (int idx = tid; idx < 579*16; idx += NTHR) {
        int r = idx >> 4, c = idx & 15;
        int col = (c & 3) * 512 + u0 + (c >> 2);
        float v;
        if (r < 512)       v = R0[r*G4H + col];
        else if (r < 576)  v = W0[(3 + r - 512)*G4H + col];
        else               v = W0[(r - 576)*G4H + col];
        sW[idx] = v;
    }
    if (tid < 16) sb[tid] = b0[(tid & 3) * 512 + u0 + (tid >> 2)];
    __syncthreads();

    unsigned lg = 0;
    for (int t = 0; t < Tn; ++t) {
        float a0 = sb[cl], a1 = a0, a2 = a0, a3 = a0;
        for (int ch = 0; ch < 5; ++ch) {
            const int r0 = ch * 128;
            const int len = (ch < 4) ? 128 : 67;
            __syncthreads();
            for (int idx = tid; idx < len*64; idx += NTHR) {
                int r = idx >> 6, bb = idx & 63, rg = r0 + r;
                float v;
                if (rg < 576) {
                    v = 0.f;
                    if (t > 0) {
                        if (rg < 512) v = g_h0[(t-1)*HB + rg*64 + bb];
                        else          v = g_w [(t-1)*NB + (rg-512)*64 + bb];
                    }
                } else {
                    v = strokes[bb*(Tn*3) + t*3 + (rg - 576)];
                }
                sIn[idx] = v;
            }
            __syncthreads();
            const float4* ip = reinterpret_cast<const float4*>(sIn) + bg;
            const float*  wp = sW + r0*16 + cl;
            #pragma unroll 4
            for (int r = 0; r < len; ++r) {
                float4 hv = ip[r*16];
                float  wv = wp[r*16];
                a0 += hv.x*wv; a1 += hv.y*wv; a2 += hv.z*wv; a3 += hv.w*wv;
            }
        }
        reinterpret_cast<float4*>(sZ)[cl*16 + bg] = make_float4(a0, a1, a2, a3);
        __syncthreads();
        {
            int ul = tid >> 6, bb = tid & 63;
            float zi = sZ[(ul*4+0)*64 + bb];
            float zf = sZ[(ul*4+1)*64 + bb];
            float zg = sZ[(ul*4+2)*64 + bb];
            float zo = sZ[(ul*4+3)*64 + bb];
            int uidx = (u0 + ul) * 64 + bb;
            float c  = g_c0[uidx];
            float c2 = sigf(zf)*c + sigf(zi)*tanhf(zg);
            float h2 = sigf(zo)*tanhf(c2);
            g_c0[uidx] = c2;
            g_h0[t*HB + uidx] = h2;
        }
        gridbar(0, &lg);

        if (blockIdx.x < Bn) {
            const int b = blockIdx.x;
            const float* h2p = &g_h0[t*HB];
            int c = tid & 31, seg = tid >> 5;
            float part = 0.f;
            if (c < 30) {
                int dbase = seg * 64;
                for (int d = 0; d < 64; ++d)
                    part += h2p[(dbase + d)*64 + b] * Wd[(dbase + d)*30 + c];
            }
            sPart[seg*32 + c] = part;
            __syncthreads();
            if (tid < 30) {
                float y = bd[tid];
                #pragma unroll
                for (int s = 0; s < 8; ++s) y += sPart[s*32 + tid];
                sy[tid] = expf(y);
            }
            __syncthreads();
            if (tid < Kn) {
                float kap = g_kappa[tid*64 + b] + sy[20 + tid];
                g_kappa[tid*64 + b] = kap;
                skap[tid] = kap;
            }
            __syncthreads();
            if (tid < Un + 1) {
                float s = 0.f;
                #pragma unroll
                for (int k = 0; k < Kn; ++k) {
                    float dd  = skap[k] - (float)(tid + 1);
                    float arg = -sy[10 + k] * dd * dd;
                    if (arg < EXP_LO) arg = EXP_LO;   // Eigen pexp clamp
                    s += sy[k] * expf(arg);
                }
                swf[tid] = s;
            }
            __syncthreads();
            if (tid < Nn) {
                float acc = 0.f;
                for (int u = 0; u < Un; ++u)
                    acc += swf[u] * trans[b*(Un*Nn) + u*Nn + tid];
                g_w[t*NB + tid*64 + b] = acc;
            }
            if (tid == 0) {
                float best = swf[0]; int bi = 0;
                for (int u = 1; u < Un + 1; ++u)
                    if (swf[u] > best) { best = swf[u]; bi = u; }
                attOut[b*Tn + t] = (float)bi;
            }
        }
        gridbar(0, &lg);
    }
}

// =========================================================================
// xz projection GEMM for layers 1/2: xz[t][c][b] = x1[t]@W + b
// grid (128 colgroups, 8 t-slices)
// =========================================================================
__global__ void __launch_bounds__(NTHR)
k_xz(const float* __restrict__ W, const float* __restrict__ bias,
     const float* __restrict__ strokes, int sel)
{
    extern __shared__ float sm[];
    float* sW  = sm;
    float* sIn = sm + 579*16;
    __shared__ float sb[16];

    const float* hin = (sel == 1) ? g_h0 : g_h1;
    const int tid = threadIdx.x;
    const int u0  = blockIdx.x * 4;
    const int cl  = tid & 15;
    const int bg  = tid >> 4;
    const int colg = (cl & 3) * 512 + u0 + (cl >> 2);

    for (int idx = tid; idx < 579*16; idx += NTHR) {
        int r = idx >> 4, c = idx & 15;
        int col = (c & 3) * 512 + u0 + (c >> 2);
        sW[idx] = W[r*G4H + col];
    }
    if (tid < 16) sb[tid] = bias[(tid & 3) * 512 + u0 + (tid >> 2)];
    __syncthreads();

    const int t0 = blockIdx.y * (Tn / 8);
    const int t1 = t0 + (Tn / 8);
    for (int t = t0; t < t1; ++t) {
        float a0 = sb[cl], a1 = a0, a2 = a0, a3 = a0;
        for (int ch = 0; ch < 5; ++ch) {
            const int r0 = ch * 128;
            const int len = (ch < 4) ? 128 : 67;
            __syncthreads();
            for (int idx = tid; idx < len*64; idx += NTHR) {
                int r = idx >> 6, bb = idx & 63, rg = r0 + r;
                float v;
                if (rg < 512)      v = hin[t*HB + rg*64 + bb];
                else if (rg < 576) v = g_w[t*NB + (rg-512)*64 + bb];
                else               v = strokes[bb*(Tn*3) + t*3 + (rg - 576)];
                sIn[idx] = v;
            }
            __syncthreads();
            const float4* ip = reinterpret_cast<const float4*>(sIn) + bg;
            const float*  wp = sW + r0*16 + cl;
            #pragma unroll 4
            for (int r = 0; r < len; ++r) {
                float4 hv = ip[r*16];
                float  wv = wp[r*16];
                a0 += hv.x*wv; a1 += hv.y*wv; a2 += hv.z*wv; a3 += hv.w*wv;
            }
        }
        float4* op = reinterpret_cast<float4*>(&g_xz[t*ZB + colg*64]) + bg;
        *op = make_float4(a0, a1, a2, a3);
    }
}

// =========================================================================
// Layers 1/2 recurrent scan: z = xz[t] + h_{t-1} @ R ; LSTM pointwise.
// =========================================================================
__global__ void __launch_bounds__(NTHR, 1)
k_scan12(const float* __restrict__ R, int sel)
{
    extern __shared__ float sm[];
    float* sW  = sm;                 // 512*16
    float* sIn = sm + 512*16;        // 128*64
    __shared__ float sZ[16*64];

    float* hseq = (sel == 1) ? g_h1 : g_h2;
    float* cbuf = (sel == 1) ? g_c1 : g_c2;
    const int slot = sel;

    const int tid = threadIdx.x;
    const int u0  = blockIdx.x * 4;
    const int cl  = tid & 15;
    const int bg  = tid >> 4;
    const int colg = (cl & 3) * 512 + u0 + (cl >> 2);

    for (int idx = tid; idx < 512*16; idx += NTHR) {
        int r = idx >> 4, c = idx & 15;
        int col = (c & 3) * 512 + u0 + (c >> 2);
        sW[idx] = R[r*G4H + col];
    }
    __syncthreads();

    unsigned lg = 0;
    for (int t = 0; t < Tn; ++t) {
        float4 z0 = *(reinterpret_cast<const float4*>(&g_xz[t*ZB + colg*64]) + bg);
        float a0 = z0.x, a1 = z0.y, a2 = z0.z, a3 = z0.w;
        for (int ch = 0; ch < 4; ++ch) {
            const int r0 = ch * 128;
            __syncthreads();
            for (int idx = tid; idx < 128*64; idx += NTHR) {
                int r = idx >> 6, bb = idx & 63;
                sIn[idx] = (t > 0) ? hseq[(t-1)*HB + (r0 + r)*64 + bb] : 0.f;
            }
            __syncthreads();
            const float4* ip = reinterpret_cast<const float4*>(sIn) + bg;
            const float*  wp = sW + r0*16 + cl;
            #pragma unroll 4
            for (int r = 0; r < 128; ++r) {
                float4 hv = ip[r*16];
                float  wv = wp[r*16];
                a0 += hv.x*wv; a1 += hv.y*wv; a2 += hv.z*wv; a3 += hv.w*wv;
            }
        }
        reinterpret_cast<float4*>(sZ)[cl*16 + bg] = make_float4(a0, a1, a2, a3);
        __syncthreads();
        {
            int ul = tid >> 6, bb = tid & 63;
            float zi = sZ[(ul*4+0)*64 + bb];
            float zf = sZ[(ul*4+1)*64 + bb];
            float zg = sZ[(ul*4+2)*64 + bb];
            float zo = sZ[(ul*4+3)*64 + bb];
            int uidx = (u0 + ul) * 64 + bb;
            float c  = cbuf[uidx];
            float c2 = sigf(zf)*c + sigf(zi)*tanhf(zg);
            float h2 = sigf(zo)*tanhf(c2);
            cbuf[uidx] = c2;
            hseq[t*HB + uidx] = h2;
        }
        gridbar(slot, &lg);
    }
}

// =========================================================================
// Output GEMM: out[b][t][o] = [h0,h1,h2][t] @ Wo + bo   (grid = 800 CTAs)
// =========================================================================
__global__ void __launch_bounds__(NTHR)
k_out(const float* __restrict__ Wo, const float* __restrict__ bo,
      float* __restrict__ out)
{
    const int t = blockIdx.x;
    const int tid = threadIdx.x;
    const int c = tid & 127;
    const int b0 = (tid >> 7) * 32;
    if (c >= On) return;

    float acc[32];
    float bias = bo[c];
    #pragma unroll
    for (int i = 0; i < 32; ++i) acc[i] = bias;

    const float* hs0 = g_h0 + t*HB;
    const float* hs1 = g_h1 + t*HB;
    const float* hs2 = g_h2 + t*HB;
    for (int l = 0; l < 3; ++l) {
        const float* hp = (l == 0) ? hs0 : (l == 1) ? hs1 : hs2;
        const float* wp = Wo + (l*512)*On + c;
        for (int d = 0; d < 512; ++d) {
            float wv = wp[d*On];
            const float4* h4 = reinterpret_cast<const float4*>(hp + d*64 + b0);
            #pragma unroll
            for (int q = 0; q < 8; ++q) {
                float4 hv = h4[q];
                acc[q*4+0] += hv.x*wv; acc[q*4+1] += hv.y*wv;
                acc[q*4+2] += hv.z*wv; acc[q*4+3] += hv.w*wv;
            }
        }
    }
    #pragma unroll
    for (int i = 0; i < 32; ++i)
        out[(b0 + i)*(Tn*On) + t*On + c] = acc[i];
}

// =========================================================================
extern "C" void kernel_launch(void* const* d_in, const int* in_sizes, int n_in,
                              void* d_out, int out_size)
{
    const float* strokes = (const float*)d_in[0];
    const float* trans   = (const float*)d_in[1];
    const float* W0      = (const float*)d_in[2];
    const float* R0      = (const float*)d_in[3];
    const float* b0      = (const float*)d_in[4];
    const float* Wd      = (const float*)d_in[5];
    const float* bd      = (const float*)d_in[6];
    const float* W1      = (const float*)d_in[7];
    const float* R1      = (const float*)d_in[8];
    const float* b1      = (const float*)d_in[9];
    const float* W2      = (const float*)d_in[10];
    const float* R2      = (const float*)d_in[11];
    const float* b2      = (const float*)d_in[12];
    const float* Wo      = (const float*)d_in[13];
    const float* bo      = (const float*)d_in[14];

    float* out = (float*)d_out;
    float* att = out + (size_t)Bn * Tn * On;

    const int smem_scan0  = (579*16 + 128*64) * 4;
    const int smem_xz     = (579*16 + 128*64) * 4;
    const int smem_scan12 = (512*16 + 128*64) * 4;
    cudaFuncSetAttribute(k_scan0,  cudaFuncAttributeMaxDynamicSharedMemorySize, smem_scan0);
    cudaFuncSetAttribute(k_xz,     cudaFuncAttributeMaxDynamicSharedMemorySize, smem_xz);
    cudaFuncSetAttribute(k_scan12, cudaFuncAttributeMaxDynamicSharedMemorySize, smem_scan12);

    k_init<<<64, 256>>>();
    k_scan0<<<NCTA, NTHR, smem_scan0>>>(strokes, trans, W0, R0, b0, Wd, bd, att);
    k_xz<<<dim3(NCTA, 8), NTHR, smem_xz>>>(W1, b1, strokes, 1);
    k_scan12<<<NCTA, NTHR, smem_scan12>>>(R1, 1);
    k_xz<<<dim3(NCTA, 8), NTHR, smem_xz>>>(W2, b2, strokes, 2);
    k_scan12<<<NCTA, NTHR, smem_scan12>>>(R2, 2);
    k_out<<<Tn, NTHR>>>(Wo, bo, out);
}

// round 4
// speedup vs baseline: 2.4199x; 2.4199x over previous
#include <cuda_runtime.h>
#include <math.h>

#define Bn 64
#define Tn 800
#define Un 64
#define Nn 64
#define Kn 10
#define Hn 512
#define On 121
#define G4H 2048
#define HB (Hn*Bn)      /* 32768 */
#define NB (Nn*Bn)      /* 4096  */
#define ZB (G4H*Bn)     /* 131072 */
#define NCTA 128
#define STHR 512

// Eigen/XLA-CPU pexp clamps its argument at ln(2^-126); replicate so the
// underflow tail ties bit-exactly (argmax -> 0) like the reference.
#define EXP_LO (-87.33654f)

// ---------------- device scratch (static, no allocations) ----------------
__device__ __align__(16) float g_h0[Tn*HB];          // [t][d][b]
__device__ __align__(16) float g_h1[Tn*HB];
__device__ __align__(16) float g_h2[Tn*HB];
__device__ __align__(16) float g_w [Tn*NB];          // [t][n][b]
__device__ __align__(16) float g_xz[Tn*ZB];          // [t][col][b]
__device__ __align__(16) float g_xT[Tn*3*Bn];        // [t][dim][b]
__device__ unsigned g_barc[4];
__device__ unsigned g_barg[4];

// ---------------- grid barrier: release-count + spin poll ----------------
__device__ __forceinline__ void gridbar(int slot, unsigned* lg) {
    __threadfence();
    __syncthreads();
    if (threadIdx.x == 0) {
        unsigned target = ++(*lg);
        unsigned a = atomicAdd(&g_barc[slot], 1u);
        if (a == gridDim.x - 1) {
            g_barc[slot] = 0u;
            __threadfence();
            atomicExch(&g_barg[slot], target);
        } else {
            while (*((volatile unsigned*)&g_barg[slot]) < target) { }
        }
    }
    __syncthreads();
}

__device__ __forceinline__ float sigf(float x) { return 1.f / (1.f + expf(-x)); }

// packed fp32x2 FMA (FFMA2) — bit-identical to two scalar FFMAs
__device__ __forceinline__ void fma2(unsigned long long &acc,
                                     unsigned long long a, unsigned long long b) {
    asm("fma.rn.f32x2 %0, %1, %2, %0;" : "+l"(acc) : "l"(a), "l"(b));
}
__device__ __forceinline__ unsigned long long dup2(float w) {
    unsigned long long r;
    asm("mov.b64 %0, {%1, %1};" : "=l"(r) : "f"(w));
    return r;
}

// one K-half of the gate matvec: rows [r0, r0+len) of sIn vs sW column cl,
// 4 batches (bg) accumulated in two f32x2 registers.
__device__ __forceinline__ void gemm_half(const float* __restrict__ sW,
                                          const float* __restrict__ sIn,
                                          int r0, int len, int cl, int bg,
                                          unsigned long long &a01,
                                          unsigned long long &a23) {
    const ulonglong2* ip = reinterpret_cast<const ulonglong2*>(sIn) + r0*16 + bg;
    const float*      wp = sW + r0*16 + cl;
    #pragma unroll 8
    for (int r = 0; r < len; ++r) {
        ulonglong2 hv = ip[r*16];
        unsigned long long w2 = dup2(wp[r*16]);
        fma2(a01, hv.x, w2);
        fma2(a23, hv.y, w2);
    }
}

// ---------------- init: barrier vars + stroke transpose ------------------
__global__ void k_init(const float* __restrict__ strokes) {
    int i = blockIdx.x * blockDim.x + threadIdx.x;
    int stride = gridDim.x * blockDim.x;
    for (int j = i; j < Tn*3*Bn; j += stride) {
        int t = j / 192, rem = j % 192, dim = rem / 64, b = rem & 63;
        g_xT[j] = strokes[b*(Tn*3) + t*3 + dim];
    }
    if (i < 4) { g_barc[i] = 0u; g_barg[i] = 0u; }
}

// =========================================================================
// Layer-0 scan + attention.  128 CTAs x 512 thr persistent.
// CTA owns 4 units (16 gate cols). halves split the 579 K-rows (290/289).
// sIn rows: [0..511] h, [512..575] w, [576..578] x.
// =========================================================================
__global__ void __launch_bounds__(STHR, 1)
k_scan0(const float* __restrict__ trans,
        const float* __restrict__ W0, const float* __restrict__ R0,
        const float* __restrict__ b0, const float* __restrict__ Wd,
        const float* __restrict__ bd, float* __restrict__ attOut)
{
    extern __shared__ float sm[];
    float* sW  = sm;                    // 579*16 = 9264
    float* sIn = sm + 9264;             // 579*64 = 37056
    float* sP  = sm + 9264 + 37056;     // 2*1024
    __shared__ float sb[16];
    __shared__ float sPart[16*32];
    __shared__ float sy[32];
    __shared__ float skap[10];
    __shared__ float swf[72];

    const int tid  = threadIdx.x;
    const int half = tid >> 8;
    const int sub  = tid & 255;
    const int cl   = sub & 15;
    const int bg   = sub >> 4;
    const int u0   = blockIdx.x * 4;

    for (int idx = tid; idx < 9264; idx += STHR) {
        int r = idx >> 4, c = idx & 15;
        int col = (c & 3) * 512 + u0 + (c >> 2);
        float v;
        if (r < 512)      v = R0[r*G4H + col];
        else if (r < 576) v = W0[(3 + r - 512)*G4H + col];
        else              v = W0[(r - 576)*G4H + col];
        sW[idx] = v;
    }
    if (tid < 16) sb[tid] = b0[(tid & 3) * 512 + u0 + (tid >> 2)];
    if (tid < 10) skap[tid] = 0.f;

    float creg = 0.f;
    float4* sIn4 = reinterpret_cast<float4*>(sIn);

    // prologue: zero h/w rows, stage x[0]
    {
        float4 z = make_float4(0.f, 0.f, 0.f, 0.f);
        for (int i = tid; i < 9216; i += STHR) sIn4[i] = z;
        const float4* xsrc = reinterpret_cast<const float4*>(g_xT);
        if (tid < 48) sIn4[9216 + tid] = xsrc[tid];
    }
    __syncthreads();

    unsigned lg = 0;
    for (int t = 0; t < Tn; ++t) {
        unsigned long long a01 = 0ull, a23 = 0ull;
        if (half == 0) gemm_half(sW, sIn, 0,   290, cl, bg, a01, a23);
        else           gemm_half(sW, sIn, 290, 289, cl, bg, a01, a23);
        ulonglong2 pv; pv.x = a01; pv.y = a23;
        reinterpret_cast<ulonglong2*>(sP)[half*256 + cl*16 + bg] = pv;
        __syncthreads();
        #pragma unroll
        for (int q = 0; q < 2; ++q) {
            int j = tid + q*512;
            int c = j >> 6;
            sP[j] = sP[j] + sP[1024 + j] + sb[c];
        }
        __syncthreads();
        if (tid < 256) {
            int b = tid & 63, uu = tid >> 6;
            float zi = sP[(uu*4+0)*64 + b];
            float zf = sP[(uu*4+1)*64 + b];
            float zg = sP[(uu*4+2)*64 + b];
            float zo = sP[(uu*4+3)*64 + b];
            float c2 = sigf(zf)*creg + sigf(zi)*tanhf(zg);
            creg = c2;
            g_h0[(size_t)t*HB + (u0+uu)*64 + b] = sigf(zo)*tanhf(c2);
        }
        gridbar(0, &lg);

        // ---- attention (CTAs 0..63), overlapped with h staging on others
        if (blockIdx.x < Bn) {
            const int b = blockIdx.x;
            const float* h2p = g_h0 + (size_t)t*HB;
            int cc = tid & 31, seg = tid >> 5;
            if (cc < 30) {
                int dbase = seg * 32;
                float part = 0.f;
                #pragma unroll 8
                for (int d = 0; d < 32; ++d)
                    part += h2p[(dbase + d)*64 + b] * Wd[(dbase + d)*30 + cc];
                sPart[seg*32 + cc] = part;
            }
            __syncthreads();
            if (tid < 30) {
                float y = bd[tid];
                #pragma unroll
                for (int s = 0; s < 16; ++s) y += sPart[s*32 + tid];
                sy[tid] = expf(y);
            }
            __syncthreads();
            if (tid < Kn) skap[tid] += sy[20 + tid];
            __syncthreads();
            if (tid < Un + 1) {
                float s = 0.f;
                #pragma unroll
                for (int k = 0; k < Kn; ++k) {
                    float dd  = skap[k] - (float)(tid + 1);
                    float arg = -sy[10 + k] * dd * dd;
                    if (arg < EXP_LO) arg = EXP_LO;   // Eigen pexp clamp
                    s += sy[k] * expf(arg);
                }
                swf[tid] = s;
            }
            __syncthreads();
            if (tid < Nn) {
                float acc = 0.f;
                #pragma unroll 8
                for (int u = 0; u < Un; ++u)
                    acc += swf[u] * trans[b*(Un*Nn) + u*Nn + tid];
                g_w[(size_t)t*NB + tid*64 + b] = acc;
            }
            if (tid == 0) {
                float best = swf[0]; int bi = 0;
                for (int u = 1; u < Un + 1; ++u)
                    if (swf[u] > best) { best = swf[u]; bi = u; }
                attOut[b*Tn + t] = (float)bi;
            }
        }

        if (t < Tn - 1) {
            // stage h rows of next step (h[t] is ready after bar1)
            const float4* src = reinterpret_cast<const float4*>(g_h0 + (size_t)t*HB);
            #pragma unroll
            for (int i = tid; i < 8192; i += STHR) sIn4[i] = src[i];
            gridbar(0, &lg);            // w[t] now complete
            const float4* wsrc = reinterpret_cast<const float4*>(g_w + (size_t)t*NB);
            #pragma unroll
            for (int i = tid; i < 1024; i += STHR) sIn4[8192 + i] = wsrc[i];
            const float4* xsrc = reinterpret_cast<const float4*>(g_xT + (size_t)(t+1)*192);
            if (tid < 48) sIn4[9216 + tid] = xsrc[tid];
            __syncthreads();
        }
    }
}

// =========================================================================
// xz projection GEMM for layers 1/2: xz[t][col][b] = x1[t]@W + b
// grid (128 colgroups, 8 t-slices) x 512 thr
// =========================================================================
__global__ void __launch_bounds__(STHR)
k_xz(const float* __restrict__ W, const float* __restrict__ bias, int sel)
{
    extern __shared__ float sm[];
    float* sW  = sm;
    float* sIn = sm + 9264;
    float* sP  = sm + 9264 + 37056;
    __shared__ float sb[16];

    const float* hin = (sel == 1) ? g_h0 : g_h1;
    const int tid  = threadIdx.x;
    const int half = tid >> 8;
    const int sub  = tid & 255;
    const int cl   = sub & 15;
    const int bg   = sub >> 4;
    const int u0   = blockIdx.x * 4;

    for (int idx = tid; idx < 9264; idx += STHR) {
        int r = idx >> 4, c = idx & 15;
        sW[idx] = W[r*G4H + (c & 3) * 512 + u0 + (c >> 2)];
    }
    if (tid < 16) sb[tid] = bias[(tid & 3) * 512 + u0 + (tid >> 2)];
    __syncthreads();

    float4* sIn4 = reinterpret_cast<float4*>(sIn);
    const int t0 = blockIdx.y * (Tn / 8);
    const int t1 = t0 + (Tn / 8);
    for (int t = t0; t < t1; ++t) {
        const float4* h4 = reinterpret_cast<const float4*>(hin + (size_t)t*HB);
        const float4* w4 = reinterpret_cast<const float4*>(g_w + (size_t)t*NB);
        const float4* x4 = reinterpret_cast<const float4*>(g_xT + (size_t)t*192);
        #pragma unroll
        for (int i = tid; i < 8192; i += STHR) sIn4[i] = h4[i];
        #pragma unroll
        for (int i = tid; i < 1024; i += STHR) sIn4[8192 + i] = w4[i];
        if (tid < 48) sIn4[9216 + tid] = x4[tid];
        __syncthreads();

        unsigned long long a01 = 0ull, a23 = 0ull;
        if (half == 0) gemm_half(sW, sIn, 0,   290, cl, bg, a01, a23);
        else           gemm_half(sW, sIn, 290, 289, cl, bg, a01, a23);
        ulonglong2 pv; pv.x = a01; pv.y = a23;
        reinterpret_cast<ulonglong2*>(sP)[half*256 + cl*16 + bg] = pv;
        __syncthreads();
        #pragma unroll
        for (int q = 0; q < 2; ++q) {
            int j = tid + q*512;
            int c = j >> 6, b = j & 63;
            int col = (c & 3) * 512 + u0 + (c >> 2);
            g_xz[(size_t)t*ZB + col*64 + b] = sP[j] + sP[1024 + j] + sb[c];
        }
    }
}

// =========================================================================
// Layers 1/2 recurrent scan: z = xz[t] + h_{t-1} @ R ; LSTM pointwise.
// =========================================================================
__global__ void __launch_bounds__(STHR, 1)
k_scan12(const float* __restrict__ R, int sel)
{
    extern __shared__ float sm[];
    float* sW  = sm;                    // 512*16 = 8192
    float* sIn = sm + 8192;             // 512*64 = 32768
    float* sP  = sm + 8192 + 32768;     // 2*1024

    float* hseq = (sel == 1) ? g_h1 : g_h2;
    const int tid  = threadIdx.x;
    const int half = tid >> 8;
    const int sub  = tid & 255;
    const int cl   = sub & 15;
    const int bg   = sub >> 4;
    const int u0   = blockIdx.x * 4;

    for (int idx = tid; idx < 8192; idx += STHR) {
        int r = idx >> 4, c = idx & 15;
        sW[idx] = R[r*G4H + (c & 3) * 512 + u0 + (c >> 2)];
    }
    float creg = 0.f;
    __syncthreads();

    float4* sIn4 = reinterpret_cast<float4*>(sIn);
    unsigned lg = 0;
    for (int t = 0; t < Tn; ++t) {
        if (t > 0) {
            const float4* src = reinterpret_cast<const float4*>(hseq + (size_t)(t-1)*HB);
            #pragma unroll
            for (int i = tid; i < 8192; i += STHR) sIn4[i] = src[i];
        } else {
            float4 z = make_float4(0.f, 0.f, 0.f, 0.f);
            #pragma unroll
            for (int i = tid; i < 8192; i += STHR) sIn4[i] = z;
        }
        __syncthreads();

        unsigned long long a01 = 0ull, a23 = 0ull;
        gemm_half(sW, sIn, half*256, 256, cl, bg, a01, a23);
        ulonglong2 pv; pv.x = a01; pv.y = a23;
        reinterpret_cast<ulonglong2*>(sP)[half*256 + cl*16 + bg] = pv;
        __syncthreads();
        #pragma unroll
        for (int q = 0; q < 2; ++q) {
            int j = tid + q*512;
            int c = j >> 6, b = j & 63;
            int col = (c & 3) * 512 + u0 + (c >> 2);
            sP[j] = sP[j] + sP[1024 + j] + g_xz[(size_t)t*ZB + col*64 + b];
        }
        __syncthreads();
        if (tid < 256) {
            int b = tid & 63, uu = tid >> 6;
            float zi = sP[(uu*4+0)*64 + b];
            float zf = sP[(uu*4+1)*64 + b];
            float zg = sP[(uu*4+2)*64 + b];
            float zo = sP[(uu*4+3)*64 + b];
            float c2 = sigf(zf)*creg + sigf(zi)*tanhf(zg);
            creg = c2;
            hseq[(size_t)t*HB + (u0+uu)*64 + b] = sigf(zo)*tanhf(c2);
        }
        gridbar(sel, &lg);
    }
}

// =========================================================================
// Output GEMM: out[b][t][o] = [h0,h1,h2][t] @ Wo + bo   (grid = 800 CTAs)
// =========================================================================
__global__ void __launch_bounds__(256)
k_out(const float* __restrict__ Wo, const float* __restrict__ bo,
      float* __restrict__ out)
{
    const int t = blockIdx.x;
    const int tid = threadIdx.x;
    const int c = tid & 127;
    const int b0 = (tid >> 7) * 32;
    if (c >= On) return;

    float acc[32];
    float bias = bo[c];
    #pragma unroll
    for (int i = 0; i < 32; ++i) acc[i] = bias;

    const float* hs0 = g_h0 + (size_t)t*HB;
    const float* hs1 = g_h1 + (size_t)t*HB;
    const float* hs2 = g_h2 + (size_t)t*HB;
    for (int l = 0; l < 3; ++l) {
        const float* hp = (l == 0) ? hs0 : (l == 1) ? hs1 : hs2;
        const float* wp = Wo + (l*512)*On + c;
        for (int d = 0; d < 512; ++d) {
            float wv = wp[d*On];
            const float4* h4 = reinterpret_cast<const float4*>(hp + d*64 + b0);
            #pragma unroll
            for (int q = 0; q < 8; ++q) {
                float4 hv = h4[q];
                acc[q*4+0] += hv.x*wv; acc[q*4+1] += hv.y*wv;
                acc[q*4+2] += hv.z*wv; acc[q*4+3] += hv.w*wv;
            }
        }
    }
    #pragma unroll
    for (int i = 0; i < 32; ++i)
        out[(size_t)(b0 + i)*(Tn*On) + t*On + c] = acc[i];
}

// =========================================================================
extern "C" void kernel_launch(void* const* d_in, const int* in_sizes, int n_in,
                              void* d_out, int out_size)
{
    const float* strokes = (const float*)d_in[0];
    const float* trans   = (const float*)d_in[1];
    const float* W0      = (const float*)d_in[2];
    const float* R0      = (const float*)d_in[3];
    const float* b0      = (const float*)d_in[4];
    const float* Wd      = (const float*)d_in[5];
    const float* bd      = (const float*)d_in[6];
    const float* W1      = (const float*)d_in[7];
    const float* R1      = (const float*)d_in[8];
    const float* b1      = (const float*)d_in[9];
    const float* W2      = (const float*)d_in[10];
    const float* R2      = (const float*)d_in[11];
    const float* b2      = (const float*)d_in[12];
    const float* Wo      = (const float*)d_in[13];
    const float* bo      = (const float*)d_in[14];

    float* out = (float*)d_out;
    float* att = out + (size_t)Bn * Tn * On;

    const int smem_big   = (9264 + 37056 + 2048) * 4;   // 193472 (scan0, xz)
    const int smem_small = (8192 + 32768 + 2048) * 4;   // 172032 (scan12)
    cudaFuncSetAttribute(k_scan0,  cudaFuncAttributeMaxDynamicSharedMemorySize, smem_big);
    cudaFuncSetAttribute(k_xz,     cudaFuncAttributeMaxDynamicSharedMemorySize, smem_big);
    cudaFuncSetAttribute(k_scan12, cudaFuncAttributeMaxDynamicSharedMemorySize, smem_small);

    k_init<<<256, 256>>>(strokes);
    k_scan0<<<NCTA, STHR, smem_big>>>(trans, W0, R0, b0, Wd, bd, att);
    k_xz<<<dim3(NCTA, 8), STHR, smem_big>>>(W1, b1, 1);
    k_scan12<<<NCTA, STHR, smem_small>>>(R1, 1);
    k_xz<<<dim3(NCTA, 8), STHR, smem_big>>>(W2, b2, 2);
    k_scan12<<<NCTA, STHR, smem_small>>>(R2, 2);
    k_out<<<Tn, 256>>>(Wo, bo, out);
}

// round 5
// speedup vs baseline: 4.1068x; 1.6971x over previous
#include <cuda_runtime.h>
#include <math.h>

#define Bn 64
#define Tn 800
#define Un 64
#define Nn 64
#define Kn 10
#define Hn 512
#define On 121
#define G4H 2048
#define HB (Hn*Bn)      /* 32768 */
#define NB (Nn*Bn)      /* 4096  */
#define ZB (G4H*Bn)     /* 131072 */
#define NCTA 128

typedef unsigned long long ull;

// Eigen/XLA-CPU pexp clamps its argument at ln(2^-126); replicate so the
// underflow tail ties bit-exactly (argmax -> 0) like the reference.
#define EXP_LO (-87.33654f)

// ---------------- device scratch (static, no allocations) ----------------
__device__ __align__(16) float g_h0[Tn*HB];          // [t][d][b]
__device__ __align__(16) float g_h1[Tn*HB];
__device__ __align__(16) float g_h2[Tn*HB];
__device__ __align__(16) float g_w [Tn*NB];          // [t][n][b]
__device__ __align__(16) float g_xz[Tn*ZB];          // [t][col][b]
__device__ __align__(16) float g_xT[Tn*3*Bn];        // [t][dim][b]
__device__ unsigned g_barc[4];                       // monotone barrier counters

// ---------------- fp32x2 helpers -----------------------------------------
__device__ __forceinline__ void fma2(ull &acc, ull a, ull b) {
    asm("fma.rn.f32x2 %0, %1, %2, %0;" : "+l"(acc) : "l"(a), "l"(b));
}
__device__ __forceinline__ ull dup2(float w) {
    ull r; asm("mov.b64 %0, {%1, %1};" : "=l"(r) : "f"(w)); return r;
}

struct Acc8 {
    ull v[8];
    __device__ __forceinline__ void zero() {
        #pragma unroll
        for (int i = 0; i < 8; ++i) v[i] = 0ull;
    }
};

// one MAC row: 16B of input (4 batches), float4 of weights (4 cols) -> 8 FFMA2
#define MAC_STEP(A, gp, wp, r)                                                   \
  { ulonglong2 in_ = *reinterpret_cast<const ulonglong2*>((gp) + (size_t)(r)*64);\
    float4 w4_ = *reinterpret_cast<const float4*>((wp) + (r)*16);                \
    ull wx_=dup2(w4_.x), wy_=dup2(w4_.y), wz_=dup2(w4_.z), ww_=dup2(w4_.w);      \
    fma2((A).v[0], in_.x, wx_); fma2((A).v[1], in_.y, wx_);                      \
    fma2((A).v[2], in_.x, wy_); fma2((A).v[3], in_.y, wy_);                      \
    fma2((A).v[4], in_.x, wz_); fma2((A).v[5], in_.y, wz_);                      \
    fma2((A).v[6], in_.x, ww_); fma2((A).v[7], in_.y, ww_); }

__device__ __forceinline__ void mac_n8u(Acc8& A, const float* __restrict__ gp,
                                        const float* __restrict__ wp, int n) {
    #pragma unroll 8
    for (int r = 0; r < n; ++r) MAC_STEP(A, gp, wp, r)
}
__device__ __forceinline__ void mac_n4u(Acc8& A, const float* __restrict__ gp,
                                        const float* __restrict__ wp, int n) {
    #pragma unroll 4
    for (int r = 0; r < n; ++r) MAC_STEP(A, gp, wp, r)
}

__device__ __forceinline__ void store_partials(float* sP, int ks, int cg, int bg,
                                               const Acc8& A) {
    float* pp = sP + ks*1024 + cg*256 + bg*4;
    *reinterpret_cast<ulonglong2*>(pp +   0) = make_ulonglong2(A.v[0], A.v[1]);
    *reinterpret_cast<ulonglong2*>(pp +  64) = make_ulonglong2(A.v[2], A.v[3]);
    *reinterpret_cast<ulonglong2*>(pp + 128) = make_ulonglong2(A.v[4], A.v[5]);
    *reinterpret_cast<ulonglong2*>(pp + 192) = make_ulonglong2(A.v[6], A.v[7]);
}

__device__ __forceinline__ float sigf(float x) { return 1.f / (1.f + expf(-x)); }

// combined arrive+wait barrier on monotone counter
__device__ __forceinline__ void bar_combined(int slot, unsigned target) {
    __threadfence();
    __syncthreads();
    if (threadIdx.x == 0) {
        atomicAdd(&g_barc[slot], 1u);
        while (*((volatile unsigned*)&g_barc[slot]) < target) { }
    }
    __syncthreads();
}

// ---------------- init: barrier vars + stroke transpose ------------------
__global__ void k_init(const float* __restrict__ strokes) {
    int i = blockIdx.x * blockDim.x + threadIdx.x;
    int stride = gridDim.x * blockDim.x;
    for (int j = i; j < Tn*3*Bn; j += stride) {
        int t = j / 192, rem = j % 192, dim = rem / 64, b = rem & 63;
        g_xT[j] = strokes[b*(Tn*3) + t*3 + dim];
    }
    if (i < 4) g_barc[i] = 0u;
}

// =========================================================================
// Layer-0 scan + attention.  128 CTAs x 512 thr persistent.
// thread: ks = tid>>6 (K-slice), cg = col-group (4 cols), bg = 4 batches.
// slot0 = "h[t] ready" (S1), slot1 = "w[t] ready" (S2).
// =========================================================================
__global__ void __launch_bounds__(512, 1)
k_scan0(const float* __restrict__ trans,
        const float* __restrict__ W0, const float* __restrict__ R0,
        const float* __restrict__ b0, const float* __restrict__ Wd,
        const float* __restrict__ bd, float* __restrict__ attOut)
{
    extern __shared__ float sm[];
    float* sW = sm;                  // 579*16 = 9264
    float* sP = sm + 9264;           // 8*16*64 = 8192
    __shared__ float sb[16];
    __shared__ float sPart[16*32];
    __shared__ float sy[32];
    __shared__ float skap[10];
    __shared__ float swf[72];

    const int tid  = threadIdx.x;
    const int lane = tid & 31;
    const int bg   = lane & 15;
    const int cg   = ((tid >> 5) & 1) * 2 + (lane >> 4);
    const int ks   = tid >> 6;
    const int u0   = blockIdx.x * 4;

    // stage weights (rows: 0..511 R0, 512..575 W0[3..66], 576..578 W0[0..2])
    for (int idx = tid; idx < 9264; idx += 512) {
        int r = idx >> 4, c = idx & 15;
        int col = (c & 3) * 512 + u0 + (c >> 2);
        float v;
        if (r < 512)      v = R0[r*G4H + col];
        else if (r < 576) v = W0[(3 + r - 512)*G4H + col];
        else              v = W0[(r - 576)*G4H + col];
        sW[idx] = v;
    }
    if (tid < 16) sb[tid] = b0[(tid & 3) * 512 + u0 + (tid >> 2)];
    if (tid < 10) skap[tid] = 0.f;
    __syncthreads();

    float creg = 0.f;

    for (int t = 0; t < Tn; ++t) {
        Acc8 A; A.zero();
        // part A: h rows (needs h[t-1], guaranteed by S1 of prev step)
        if (t > 0)
            mac_n8u(A, g_h0 + (size_t)(t-1)*HB + (ks*64)*64 + bg*4,
                    sW + (ks*64)*16 + cg*4, 64);
        // x rows (3, on ks==7)
        if (ks == 7)
            mac_n4u(A, g_xT + (size_t)t*192 + bg*4, sW + 576*16 + cg*4, 3);
        // wait S2: w[t-1] ready
        if (tid == 0) {
            unsigned tgt = (unsigned)t * NCTA;
            while (*((volatile unsigned*)&g_barc[1]) < tgt) { }
        }
        __syncthreads();
        // part B: w rows (8, per ks)
        if (t > 0)
            mac_n4u(A, g_w + (size_t)(t-1)*NB + (ks*8)*64 + bg*4,
                    sW + (512 + ks*8)*16 + cg*4, 8);

        store_partials(sP, ks, cg, bg, A);
        __syncthreads();
        #pragma unroll
        for (int q = 0; q < 2; ++q) {
            int j = tid + q*512;
            float s = sb[j >> 6];
            #pragma unroll
            for (int k = 0; k < 8; ++k) s += sP[k*1024 + j];
            sP[j] = s;
        }
        __syncthreads();
        if (tid < 256) {
            int b = tid & 63, uu = tid >> 6;
            float zi = sP[(uu*4+0)*64 + b];
            float zf = sP[(uu*4+1)*64 + b];
            float zg = sP[(uu*4+2)*64 + b];
            float zo = sP[(uu*4+3)*64 + b];
            float c2 = sigf(zf)*creg + sigf(zi)*tanhf(zg);
            creg = c2;
            g_h0[(size_t)t*HB + (u0+uu)*64 + b] = sigf(zo)*tanhf(c2);
        }
        // S1: h[t] ready everywhere
        bar_combined(0, (unsigned)(t+1) * NCTA);

        // attention on CTAs 0..63; others arrive S2 immediately and proceed
        if (blockIdx.x < Bn) {
            const int b = blockIdx.x;
            const float* h2p = g_h0 + (size_t)t*HB;
            int cc = tid & 31, seg = tid >> 5;
            if (cc < 30) {
                int dbase = seg * 32;
                float part = 0.f;
                #pragma unroll 8
                for (int d = 0; d < 32; ++d)
                    part += h2p[(dbase + d)*64 + b] * Wd[(dbase + d)*30 + cc];
                sPart[seg*32 + cc] = part;
            }
            __syncthreads();
            if (tid < 30) {
                float y = bd[tid];
                #pragma unroll
                for (int s = 0; s < 16; ++s) y += sPart[s*32 + tid];
                sy[tid] = expf(y);
            }
            __syncthreads();
            if (tid < Kn) skap[tid] += sy[20 + tid];
            __syncthreads();
            if (tid < Un + 1) {
                float s = 0.f;
                #pragma unroll
                for (int k = 0; k < Kn; ++k) {
                    float dd  = skap[k] - (float)(tid + 1);
                    float arg = -sy[10 + k] * dd * dd;
                    if (arg < EXP_LO) arg = EXP_LO;   // Eigen pexp clamp
                    s += sy[k] * expf(arg);
                }
                swf[tid] = s;
            }
            __syncthreads();
            if (tid < Nn) {
                float acc = 0.f;
                #pragma unroll 8
                for (int u = 0; u < Un; ++u)
                    acc += swf[u] * trans[b*(Un*Nn) + u*Nn + tid];
                g_w[(size_t)t*NB + tid*64 + b] = acc;
            }
            if (tid == 0) {
                float best = swf[0]; int bi = 0;
                for (int u = 1; u < Un + 1; ++u)
                    if (swf[u] > best) { best = swf[u]; bi = u; }
                attOut[b*Tn + t] = (float)bi;
            }
            __threadfence();
            __syncthreads();
            if (tid == 0) atomicAdd(&g_barc[1], 1u);   // S2 arrive (w[t] done)
        } else {
            if (tid == 0) atomicAdd(&g_barc[1], 1u);   // S2 arrive (vacuous)
        }
    }
}

// =========================================================================
// xz projection GEMM for layers 1/2: xz[t][col][b] = x1[t]@W + b
// grid (128 colgroups, 8 t-slices) x 512 thr, 2 CTAs/SM
// =========================================================================
__global__ void __launch_bounds__(512, 2)
k_xz(const float* __restrict__ W, const float* __restrict__ bias, int sel)
{
    extern __shared__ float sm[];
    float* sW = sm;                  // 9264
    float* sP = sm + 9264;           // 8192
    __shared__ float sb[16];

    const float* hin = (sel == 1) ? g_h0 : g_h1;
    const int tid  = threadIdx.x;
    const int lane = tid & 31;
    const int bg   = lane & 15;
    const int cg   = ((tid >> 5) & 1) * 2 + (lane >> 4);
    const int ks   = tid >> 6;
    const int u0   = blockIdx.x * 4;

    for (int idx = tid; idx < 9264; idx += 512) {
        int r = idx >> 4, c = idx & 15;
        sW[idx] = W[r*G4H + (c & 3) * 512 + u0 + (c >> 2)];
    }
    if (tid < 16) sb[tid] = bias[(tid & 3) * 512 + u0 + (tid >> 2)];
    __syncthreads();

    const int t0 = blockIdx.y * (Tn / 8);
    const int t1 = t0 + (Tn / 8);
    for (int t = t0; t < t1; ++t) {
        Acc8 A; A.zero();
        mac_n4u(A, hin + (size_t)t*HB + (ks*64)*64 + bg*4,
                sW + (ks*64)*16 + cg*4, 64);
        mac_n4u(A, g_w + (size_t)t*NB + (ks*8)*64 + bg*4,
                sW + (512 + ks*8)*16 + cg*4, 8);
        if (ks == 7)
            mac_n4u(A, g_xT + (size_t)t*192 + bg*4, sW + 576*16 + cg*4, 3);

        store_partials(sP, ks, cg, bg, A);
        __syncthreads();
        #pragma unroll
        for (int q = 0; q < 2; ++q) {
            int j = tid + q*512;
            int c = j >> 6, b = j & 63;
            float s = sb[c];
            #pragma unroll
            for (int k = 0; k < 8; ++k) s += sP[k*1024 + j];
            int col = (c & 3) * 512 + u0 + (c >> 2);
            g_xz[(size_t)t*ZB + col*64 + b] = s;
        }
        __syncthreads();
    }
}

// =========================================================================
// Layers 1/2 recurrent scan: z = xz[t] + h_{t-1} @ R ; LSTM pointwise.
// =========================================================================
__global__ void __launch_bounds__(512, 1)
k_scan12(const float* __restrict__ R, int sel)
{
    extern __shared__ float sm[];
    float* sW = sm;                  // 512*16 = 8192
    float* sP = sm + 8192;           // 8192

    float* hseq = (sel == 1) ? g_h1 : g_h2;
    const int slot = sel + 1;        // 2 or 3
    const int tid  = threadIdx.x;
    const int lane = tid & 31;
    const int bg   = lane & 15;
    const int cg   = ((tid >> 5) & 1) * 2 + (lane >> 4);
    const int ks   = tid >> 6;
    const int u0   = blockIdx.x * 4;

    for (int idx = tid; idx < 8192; idx += 512) {
        int r = idx >> 4, c = idx & 15;
        sW[idx] = R[r*G4H + (c & 3) * 512 + u0 + (c >> 2)];
    }
    float creg = 0.f;
    __syncthreads();

    for (int t = 0; t < Tn; ++t) {
        Acc8 A; A.zero();
        if (t > 0)
            mac_n8u(A, hseq + (size_t)(t-1)*HB + (ks*64)*64 + bg*4,
                    sW + (ks*64)*16 + cg*4, 64);
        store_partials(sP, ks, cg, bg, A);
        __syncthreads();
        #pragma unroll
        for (int q = 0; q < 2; ++q) {
            int j = tid + q*512;
            int c = j >> 6, b = j & 63;
            int col = (c & 3) * 512 + u0 + (c >> 2);
            float s = g_xz[(size_t)t*ZB + col*64 + b];
            #pragma unroll
            for (int k = 0; k < 8; ++k) s += sP[k*1024 + j];
            sP[j] = s;
        }
        __syncthreads();
        if (tid < 256) {
            int b = tid & 63, uu = tid >> 6;
            float zi = sP[(uu*4+0)*64 + b];
            float zf = sP[(uu*4+1)*64 + b];
            float zg = sP[(uu*4+2)*64 + b];
            float zo = sP[(uu*4+3)*64 + b];
            float c2 = sigf(zf)*creg + sigf(zi)*tanhf(zg);
            creg = c2;
            hseq[(size_t)t*HB + (u0+uu)*64 + b] = sigf(zo)*tanhf(c2);
        }
        bar_combined(slot, (unsigned)(t+1) * NCTA);
    }
}

// =========================================================================
// Output GEMM: out[b][t][o] = [h0,h1,h2][t] @ Wo + bo   (grid = 800 CTAs)
// =========================================================================
__global__ void __launch_bounds__(256)
k_out(const float* __restrict__ Wo, const float* __restrict__ bo,
      float* __restrict__ out)
{
    const int t = blockIdx.x;
    const int tid = threadIdx.x;
    const int c = tid & 127;
    const int b0 = (tid >> 7) * 32;
    if (c >= On) return;

    float acc[32];
    float bias = bo[c];
    #pragma unroll
    for (int i = 0; i < 32; ++i) acc[i] = bias;

    const float* hs0 = g_h0 + (size_t)t*HB;
    const float* hs1 = g_h1 + (size_t)t*HB;
    const float* hs2 = g_h2 + (size_t)t*HB;
    for (int l = 0; l < 3; ++l) {
        const float* hp = (l == 0) ? hs0 : (l == 1) ? hs1 : hs2;
        const float* wp = Wo + (l*512)*On + c;
        for (int d = 0; d < 512; ++d) {
            float wv = wp[d*On];
            const float4* h4 = reinterpret_cast<const float4*>(hp + d*64 + b0);
            #pragma unroll
            for (int q = 0; q < 8; ++q) {
                float4 hv = h4[q];
                acc[q*4+0] += hv.x*wv; acc[q*4+1] += hv.y*wv;
                acc[q*4+2] += hv.z*wv; acc[q*4+3] += hv.w*wv;
            }
        }
    }
    #pragma unroll
    for (int i = 0; i < 32; ++i)
        out[(size_t)(b0 + i)*(Tn*On) + t*On + c] = acc[i];
}

// =========================================================================
extern "C" void kernel_launch(void* const* d_in, const int* in_sizes, int n_in,
                              void* d_out, int out_size)
{
    const float* strokes = (const float*)d_in[0];
    const float* trans   = (const float*)d_in[1];
    const float* W0      = (const float*)d_in[2];
    const float* R0      = (const float*)d_in[3];
    const float* b0      = (const float*)d_in[4];
    const float* Wd      = (const float*)d_in[5];
    const float* bd      = (const float*)d_in[6];
    const float* W1      = (const float*)d_in[7];
    const float* R1      = (const float*)d_in[8];
    const float* b1      = (const float*)d_in[9];
    const float* W2      = (const float*)d_in[10];
    const float* R2      = (const float*)d_in[11];
    const float* b2      = (const float*)d_in[12];
    const float* Wo      = (const float*)d_in[13];
    const float* bo      = (const float*)d_in[14];

    float* out = (float*)d_out;
    float* att = out + (size_t)Bn * Tn * On;

    const int smem_scan0  = (9264 + 8192) * 4;   // 69824
    const int smem_xz     = (9264 + 8192) * 4;   // 69824
    const int smem_scan12 = (8192 + 8192) * 4;   // 65536
    cudaFuncSetAttribute(k_scan0,  cudaFuncAttributeMaxDynamicSharedMemorySize, smem_scan0);
    cudaFuncSetAttribute(k_xz,     cudaFuncAttributeMaxDynamicSharedMemorySize, smem_xz);
    cudaFuncSetAttribute(k_scan12, cudaFuncAttributeMaxDynamicSharedMemorySize, smem_scan12);

    k_init<<<256, 256>>>(strokes);
    k_scan0<<<NCTA, 512, smem_scan0>>>(trans, W0, R0, b0, Wd, bd, att);
    k_xz<<<dim3(NCTA, 8), 512, smem_xz>>>(W1, b1, 1);
    k_scan12<<<NCTA, 512, smem_scan12>>>(R1, 1);
    k_xz<<<dim3(NCTA, 8), 512, smem_xz>>>(W2, b2, 2);
    k_scan12<<<NCTA, 512, smem_scan12>>>(R2, 2);
    k_out<<<Tn, 256>>>(Wo, bo, out);
}

// round 6
// speedup vs baseline: 4.3476x; 1.0586x over previous
#include <cuda_runtime.h>
#include <math.h>

#define Bn 64
#define Tn 800
#define Un 64
#define Nn 64
#define Kn 10
#define Hn 512
#define On 121
#define G4H 2048
#define HB (Hn*Bn)      /* 32768 */
#define NB (Nn*Bn)      /* 4096  */
#define ZB (G4H*Bn)     /* 131072 */
#define NCTA 128

typedef unsigned long long ull;

// Eigen/XLA-CPU pexp clamps its argument at ln(2^-126); replicate so the
// underflow tail ties bit-exactly (argmax -> 0) like the reference.
#define EXP_LO (-87.33654f)

// ---------------- device scratch (static, no allocations) ----------------
__device__ __align__(16) float g_h0[Tn*HB];          // [t][d][b]
__device__ __align__(16) float g_h1[Tn*HB];
__device__ __align__(16) float g_h2[Tn*HB];
__device__ __align__(16) float g_w [Tn*NB];          // [t][n][b]
__device__ __align__(16) float g_xz[Tn*ZB];          // [t][col][b]
__device__ __align__(16) float g_xT[Tn*3*Bn];        // [t][dim][b]
__device__ unsigned g_barc[4];                       // monotone barrier counters

// ---------------- fp32x2 helpers -----------------------------------------
__device__ __forceinline__ void fma2(ull &acc, ull a, ull b) {
    asm("fma.rn.f32x2 %0, %1, %2, %0;" : "+l"(acc) : "l"(a), "l"(b));
}
__device__ __forceinline__ ull dup2(float w) {
    ull r; asm("mov.b64 %0, {%1, %1};" : "=l"(r) : "f"(w)); return r;
}
__device__ __forceinline__ void unpack2(ull v, float &lo, float &hi) {
    asm("mov.b64 {%0, %1}, %2;" : "=f"(lo), "=f"(hi) : "l"(v));
}

struct Acc8 {
    ull v[8];
    __device__ __forceinline__ void zero() {
        #pragma unroll
        for (int i = 0; i < 8; ++i) v[i] = 0ull;
    }
};

__device__ __forceinline__ void mac_core(Acc8 &A, ulonglong2 in_, float4 w4_) {
    ull wx_ = dup2(w4_.x), wy_ = dup2(w4_.y), wz_ = dup2(w4_.z), ww_ = dup2(w4_.w);
    fma2(A.v[0], in_.x, wx_); fma2(A.v[1], in_.y, wx_);
    fma2(A.v[2], in_.x, wy_); fma2(A.v[3], in_.y, wy_);
    fma2(A.v[4], in_.x, wz_); fma2(A.v[5], in_.y, wz_);
    fma2(A.v[6], in_.x, ww_); fma2(A.v[7], in_.y, ww_);
}

// software-pipelined 64-row MAC: prefetch next 4 rows while FMA-ing current 4
__device__ __forceinline__ void gemm_pipe64(Acc8 &A, const float* __restrict__ gp,
                                            const float* __restrict__ wp) {
    ulonglong2 in_cur[4]; float4 w_cur[4];
    #pragma unroll
    for (int i = 0; i < 4; ++i) {
        in_cur[i] = *reinterpret_cast<const ulonglong2*>(gp + (size_t)i*64);
        w_cur[i]  = *reinterpret_cast<const float4*>(wp + i*16);
    }
    #pragma unroll
    for (int b = 0; b < 16; ++b) {
        ulonglong2 in_nxt[4]; float4 w_nxt[4];
        if (b < 15) {
            #pragma unroll
            for (int i = 0; i < 4; ++i) {
                in_nxt[i] = *reinterpret_cast<const ulonglong2*>(gp + (size_t)(b*4+4+i)*64);
                w_nxt[i]  = *reinterpret_cast<const float4*>(wp + (b*4+4+i)*16);
            }
        }
        #pragma unroll
        for (int i = 0; i < 4; ++i) mac_core(A, in_cur[i], w_cur[i]);
        if (b < 15) {
            #pragma unroll
            for (int i = 0; i < 4; ++i) { in_cur[i] = in_nxt[i]; w_cur[i] = w_nxt[i]; }
        }
    }
}

__device__ __forceinline__ void mac_n4u(Acc8 &A, const float* __restrict__ gp,
                                        const float* __restrict__ wp, int n) {
    #pragma unroll 4
    for (int r = 0; r < n; ++r) {
        ulonglong2 in_ = *reinterpret_cast<const ulonglong2*>(gp + (size_t)r*64);
        float4 w4_ = *reinterpret_cast<const float4*>(wp + r*16);
        mac_core(A, in_, w4_);
    }
}

__device__ __forceinline__ void store_partials(float* sP, int ks, int cg, int bg,
                                               const Acc8& A) {
    float* pp = sP + ks*1024 + cg*256 + bg*4;
    *reinterpret_cast<ulonglong2*>(pp +   0) = make_ulonglong2(A.v[0], A.v[1]);
    *reinterpret_cast<ulonglong2*>(pp +  64) = make_ulonglong2(A.v[2], A.v[3]);
    *reinterpret_cast<ulonglong2*>(pp + 128) = make_ulonglong2(A.v[4], A.v[5]);
    *reinterpret_cast<ulonglong2*>(pp + 192) = make_ulonglong2(A.v[6], A.v[7]);
}

// fast gates (~1e-6 rel err): safe for LSTM nonlinearities
__device__ __forceinline__ float sigf2(float x) {
    return __fdividef(1.f, 1.f + __expf(-x));
}
__device__ __forceinline__ float tanhf2(float x) {
    return 1.f - __fdividef(2.f, __expf(2.f*x) + 1.f);
}

// ---------------- release/acquire barrier primitives ---------------------
__device__ __forceinline__ void bar_arrive(int slot) {
    asm volatile("red.release.gpu.global.add.u32 [%0], 1;"
                 :: "l"(g_barc + slot) : "memory");
}
__device__ __forceinline__ void bar_wait_ge(int slot, unsigned target) {
    unsigned v;
    do {
        asm volatile("ld.acquire.gpu.global.u32 %0, [%1];"
                     : "=r"(v) : "l"(g_barc + slot) : "memory");
    } while (v < target);
}
// combined arrive+wait (CTA-wide)
__device__ __forceinline__ void bar_epoch(int slot, unsigned target) {
    __syncthreads();
    if (threadIdx.x == 0) { bar_arrive(slot); bar_wait_ge(slot, target); }
    __syncthreads();
}

// ---------------- init: barrier vars + stroke transpose ------------------
__global__ void k_init(const float* __restrict__ strokes) {
    int i = blockIdx.x * blockDim.x + threadIdx.x;
    int stride = gridDim.x * blockDim.x;
    for (int j = i; j < Tn*3*Bn; j += stride) {
        int t = j / 192, rem = j % 192, dim = rem / 64, b = rem & 63;
        g_xT[j] = strokes[b*(Tn*3) + t*3 + dim];
    }
    if (i < 4) g_barc[i] = 0u;
}

// =========================================================================
// Layer-0 scan + attention.  128 CTAs x 512 thr persistent.
// thread: ks = tid>>6 (K-slice), cg = col-group (4 cols), bg = 4 batches.
// slot0 = "h[t] ready" (S1), slot1 = "w[t] ready" (S2).
// =========================================================================
__global__ void __launch_bounds__(512, 1)
k_scan0(const float* __restrict__ trans,
        const float* __restrict__ W0, const float* __restrict__ R0,
        const float* __restrict__ b0, const float* __restrict__ Wd,
        const float* __restrict__ bd, float* __restrict__ attOut)
{
    extern __shared__ float sm[];
    float* sW = sm;                  // 579*16 = 9264
    float* sP = sm + 9264;           // 8*16*64 = 8192
    __shared__ float sb[16];
    __shared__ float sPart[16*32];
    __shared__ float sy[32];
    __shared__ float skap[10];
    __shared__ float swf[72];

    const int tid  = threadIdx.x;
    const int lane = tid & 31;
    const int bg   = lane & 15;
    const int cg   = ((tid >> 5) & 1) * 2 + (lane >> 4);
    const int ks   = tid >> 6;
    const int u0   = blockIdx.x * 4;
    const int bR   = tid & 63;       // reduce: batch
    const int uuR  = tid >> 6;       // reduce: unit (tid<256)

    // stage weights (rows: 0..511 R0, 512..575 W0[3..66], 576..578 W0[0..2])
    for (int idx = tid; idx < 9264; idx += 512) {
        int r = idx >> 4, c = idx & 15;
        int col = (c & 3) * 512 + u0 + (c >> 2);
        float v;
        if (r < 512)      v = R0[r*G4H + col];
        else if (r < 576) v = W0[(3 + r - 512)*G4H + col];
        else              v = W0[(r - 576)*G4H + col];
        sW[idx] = v;
    }
    if (tid < 16) sb[tid] = b0[(tid & 3) * 512 + u0 + (tid >> 2)];
    if (tid < 10) skap[tid] = 0.f;
    __syncthreads();

    float creg = 0.f;

    for (int t = 0; t < Tn; ++t) {
        Acc8 A; A.zero();
        // part A: h rows (h[t-1] guaranteed by S1 of prev step)
        if (t > 0)
            gemm_pipe64(A, g_h0 + (size_t)(t-1)*HB + (ks*64)*64 + bg*4,
                        sW + (ks*64)*16 + cg*4);
        // x rows (3, on ks==7)
        if (ks == 7)
            mac_n4u(A, g_xT + (size_t)t*192 + bg*4, sW + 576*16 + cg*4, 3);
        // wait S2: w[t-1] ready
        if (tid == 0) bar_wait_ge(1, (unsigned)t * NCTA);
        __syncthreads();
        // part B: w rows (8, per ks)
        if (t > 0)
            mac_n4u(A, g_w + (size_t)(t-1)*NB + (ks*8)*64 + bg*4,
                    sW + (512 + ks*8)*16 + cg*4, 8);

        store_partials(sP, ks, cg, bg, A);
        __syncthreads();
        if (tid < 256) {
            float z[4];
            #pragma unroll
            for (int g = 0; g < 4; ++g) {
                float s = sb[uuR*4 + g];
                #pragma unroll
                for (int k = 0; k < 8; ++k) s += sP[k*1024 + (uuR*4+g)*64 + bR];
                z[g] = s;
            }
            float c2 = sigf2(z[1])*creg + sigf2(z[0])*tanhf2(z[2]);
            creg = c2;
            g_h0[(size_t)t*HB + (u0+uuR)*64 + bR] = sigf2(z[3])*tanhf2(c2);
        }
        // S1: h[t] ready everywhere
        bar_epoch(0, (unsigned)(t+1) * NCTA);

        // attention on CTAs 0..63; others arrive S2 immediately and proceed
        if (blockIdx.x < Bn) {
            const int b = blockIdx.x;
            const float* h2p = g_h0 + (size_t)t*HB;
            int cc = tid & 31, seg = tid >> 5;
            if (cc < 30) {
                int dbase = seg * 32;
                float part = 0.f;
                #pragma unroll 8
                for (int d = 0; d < 32; ++d)
                    part += h2p[(dbase + d)*64 + b] * Wd[(dbase + d)*30 + cc];
                sPart[seg*32 + cc] = part;
            }
            __syncthreads();
            if (tid < 30) {
                float y = bd[tid];
                #pragma unroll
                for (int s = 0; s < 16; ++s) y += sPart[s*32 + tid];
                sy[tid] = expf(y);
            }
            __syncthreads();
            if (tid < Kn) skap[tid] += sy[20 + tid];
            __syncthreads();
            if (tid < Un + 1) {
                float s = 0.f;
                #pragma unroll
                for (int k = 0; k < Kn; ++k) {
                    float dd  = skap[k] - (float)(tid + 1);
                    float arg = -sy[10 + k] * dd * dd;
                    if (arg < EXP_LO) arg = EXP_LO;   // Eigen pexp clamp
                    s += sy[k] * expf(arg);
                }
                swf[tid] = s;
            }
            __syncthreads();
            if (tid < Nn) {
                float acc = 0.f;
                #pragma unroll 8
                for (int u = 0; u < Un; ++u)
                    acc += swf[u] * trans[b*(Un*Nn) + u*Nn + tid];
                g_w[(size_t)t*NB + tid*64 + b] = acc;
            }
            if (tid == 0) {
                float best = swf[0]; int bi = 0;
                for (int u = 1; u < Un + 1; ++u)
                    if (swf[u] > best) { best = swf[u]; bi = u; }
                attOut[b*Tn + t] = (float)bi;
            }
            __syncthreads();
            if (tid == 0) bar_arrive(1);   // S2: w[t] done (release publishes w)
        } else {
            if (tid == 0) bar_arrive(1);   // S2 arrive (vacuous)
        }
    }
}

// =========================================================================
// xz projection GEMM for layers 1/2: xz[t][col][b] = x1[t]@W + b
// grid (128 colgroups, 8 t-slices) x 512 thr, 2 CTAs/SM
// =========================================================================
__global__ void __launch_bounds__(512, 2)
k_xz(const float* __restrict__ W, const float* __restrict__ bias, int sel)
{
    extern __shared__ float sm[];
    float* sW = sm;                  // 9264
    float* sP = sm + 9264;           // 8192
    __shared__ float sb[16];

    const float* hin = (sel == 1) ? g_h0 : g_h1;
    const int tid  = threadIdx.x;
    const int lane = tid & 31;
    const int bg   = lane & 15;
    const int cg   = ((tid >> 5) & 1) * 2 + (lane >> 4);
    const int ks   = tid >> 6;
    const int u0   = blockIdx.x * 4;

    for (int idx = tid; idx < 9264; idx += 512) {
        int r = idx >> 4, c = idx & 15;
        sW[idx] = W[r*G4H + (c & 3) * 512 + u0 + (c >> 2)];
    }
    if (tid < 16) sb[tid] = bias[(tid & 3) * 512 + u0 + (tid >> 2)];
    __syncthreads();

    const int t0 = blockIdx.y * (Tn / 8);
    const int t1 = t0 + (Tn / 8);
    for (int t = t0; t < t1; ++t) {
        Acc8 A; A.zero();
        mac_n4u(A, hin + (size_t)t*HB + (ks*64)*64 + bg*4,
                sW + (ks*64)*16 + cg*4, 64);
        mac_n4u(A, g_w + (size_t)t*NB + (ks*8)*64 + bg*4,
                sW + (512 + ks*8)*16 + cg*4, 8);
        if (ks == 7)
            mac_n4u(A, g_xT + (size_t)t*192 + bg*4, sW + 576*16 + cg*4, 3);

        store_partials(sP, ks, cg, bg, A);
        __syncthreads();
        #pragma unroll
        for (int q = 0; q < 2; ++q) {
            int j = tid + q*512;
            int c = j >> 6, b = j & 63;
            float s = sb[c];
            #pragma unroll
            for (int k = 0; k < 8; ++k) s += sP[k*1024 + j];
            int col = (c & 3) * 512 + u0 + (c >> 2);
            g_xz[(size_t)t*ZB + col*64 + b] = s;
        }
        __syncthreads();
    }
}

// =========================================================================
// Layers 1/2 recurrent scan: z = xz[t] + h_{t-1} @ R ; LSTM pointwise.
// =========================================================================
__global__ void __launch_bounds__(512, 1)
k_scan12(const float* __restrict__ R, int sel)
{
    extern __shared__ float sm[];
    float* sW = sm;                  // 512*16 = 8192
    float* sP = sm + 8192;           // 8192

    float* hseq = (sel == 1) ? g_h1 : g_h2;
    const int slot = sel + 1;        // 2 or 3
    const int tid  = threadIdx.x;
    const int lane = tid & 31;
    const int bg   = lane & 15;
    const int cg   = ((tid >> 5) & 1) * 2 + (lane >> 4);
    const int ks   = tid >> 6;
    const int u0   = blockIdx.x * 4;
    const int bR   = tid & 63;
    const int uuR  = tid >> 6;

    for (int idx = tid; idx < 8192; idx += 512) {
        int r = idx >> 4, c = idx & 15;
        sW[idx] = R[r*G4H + (c & 3) * 512 + u0 + (c >> 2)];
    }
    float creg = 0.f;
    __syncthreads();

    for (int t = 0; t < Tn; ++t) {
        // prefetch this step's xz for the reduce threads (hides L2 latency)
        float xzv[4];
        if (tid < 256) {
            #pragma unroll
            for (int g = 0; g < 4; ++g)
                xzv[g] = g_xz[(size_t)t*ZB + (g*512 + u0 + uuR)*64 + bR];
        }
        Acc8 A; A.zero();
        if (t > 0)
            gemm_pipe64(A, hseq + (size_t)(t-1)*HB + (ks*64)*64 + bg*4,
                        sW + (ks*64)*16 + cg*4);
        store_partials(sP, ks, cg, bg, A);
        __syncthreads();
        if (tid < 256) {
            float z[4];
            #pragma unroll
            for (int g = 0; g < 4; ++g) {
                float s = xzv[g];
                #pragma unroll
                for (int k = 0; k < 8; ++k) s += sP[k*1024 + (uuR*4+g)*64 + bR];
                z[g] = s;
            }
            float c2 = sigf2(z[1])*creg + sigf2(z[0])*tanhf2(z[2]);
            creg = c2;
            hseq[(size_t)t*HB + (u0+uuR)*64 + bR] = sigf2(z[3])*tanhf2(c2);
        }
        bar_epoch(slot, (unsigned)(t+1) * NCTA);
    }
}

// =========================================================================
// Output GEMM: out[b][t][o] = [h0,h1,h2][t] @ Wo + bo   (grid = 800 CTAs)
// fp32x2 accumulation; h loads broadcast across the warp (1 line each).
// =========================================================================
__global__ void __launch_bounds__(256)
k_out(const float* __restrict__ Wo, const float* __restrict__ bo,
      float* __restrict__ out)
{
    const int t = blockIdx.x;
    const int tid = threadIdx.x;
    const int c = tid & 127;
    const int bh = tid >> 7;            // 0/1: batches bh*32..bh*32+31
    if (c >= On) return;

    ull acc[16];
    ull bias2 = dup2(bo[c]);
    #pragma unroll
    for (int i = 0; i < 16; ++i) acc[i] = bias2;

    #pragma unroll
    for (int l = 0; l < 3; ++l) {
        const float* hp = (l == 0 ? g_h0 : l == 1 ? g_h1 : g_h2) + (size_t)t*HB;
        const float* wp = Wo + (l*512)*On + c;
        #pragma unroll 2
        for (int d = 0; d < 512; ++d) {
            ull wv = dup2(wp[d*On]);
            const ulonglong2* h4 = reinterpret_cast<const ulonglong2*>(hp + d*64 + bh*32);
            #pragma unroll
            for (int q = 0; q < 8; ++q) {
                ulonglong2 hv = h4[q];
                fma2(acc[2*q],   hv.x, wv);
                fma2(acc[2*q+1], hv.y, wv);
            }
        }
    }
    #pragma unroll
    for (int i = 0; i < 16; ++i) {
        float lo, hi; unpack2(acc[i], lo, hi);
        int b = bh*32 + 2*i;
        out[(size_t)b     *(Tn*On) + t*On + c] = lo;
        out[(size_t)(b+1) *(Tn*On) + t*On + c] = hi;
    }
}

// =========================================================================
extern "C" void kernel_launch(void* const* d_in, const int* in_sizes, int n_in,
                              void* d_out, int out_size)
{
    const float* strokes = (const float*)d_in[0];
    const float* trans   = (const float*)d_in[1];
    const float* W0      = (const float*)d_in[2];
    const float* R0      = (const float*)d_in[3];
    const float* b0      = (const float*)d_in[4];
    const float* Wd      = (const float*)d_in[5];
    const float* bd      = (const float*)d_in[6];
    const float* W1      = (const float*)d_in[7];
    const float* R1      = (const float*)d_in[8];
    const float* b1      = (const float*)d_in[9];
    const float* W2      = (const float*)d_in[10];
    const float* R2      = (const float*)d_in[11];
    const float* b2      = (const float*)d_in[12];
    const float* Wo      = (const float*)d_in[13];
    const float* bo      = (const float*)d_in[14];

    float* out = (float*)d_out;
    float* att = out + (size_t)Bn * Tn * On;

    const int smem_scan0  = (9264 + 8192) * 4;   // 69824
    const int smem_xz     = (9264 + 8192) * 4;   // 69824
    const int smem_scan12 = (8192 + 8192) * 4;   // 65536
    cudaFuncSetAttribute(k_scan0,  cudaFuncAttributeMaxDynamicSharedMemorySize, smem_scan0);
    cudaFuncSetAttribute(k_xz,     cudaFuncAttributeMaxDynamicSharedMemorySize, smem_xz);
    cudaFuncSetAttribute(k_scan12, cudaFuncAttributeMaxDynamicSharedMemorySize, smem_scan12);

    k_init<<<256, 256>>>(strokes);
    k_scan0<<<NCTA, 512, smem_scan0>>>(trans, W0, R0, b0, Wd, bd, att);
    k_xz<<<dim3(NCTA, 8), 512, smem_xz>>>(W1, b1, 1);
    k_scan12<<<NCTA, 512, smem_scan12>>>(R1, 1);
    k_xz<<<dim3(NCTA, 8), 512, smem_xz>>>(W2, b2, 2);
    k_scan12<<<NCTA, 512, smem_scan12>>>(R2, 2);
    k_out<<<Tn, 256>>>(Wo, bo, out);
}

// round 7
// speedup vs baseline: 4.9310x; 1.1342x over previous
#include <cuda_runtime.h>
#include <math.h>

#define Bn 64
#define Tn 800
#define Un 64
#define Nn 64
#define Kn 10
#define Hn 512
#define On 121
#define G4H 2048
#define HB (Hn*Bn)      /* 32768 */
#define NB (Nn*Bn)      /* 4096  */
#define ZB (G4H*Bn)     /* 131072 */
#define NCTA 128

typedef unsigned long long ull;

// Eigen/XLA-CPU pexp clamps its argument at ln(2^-126); replicate so the
// underflow tail ties bit-exactly (argmax -> 0) like the reference.
#define EXP_LO (-87.33654f)

// ---------------- device scratch (static, no allocations) ----------------
__device__ __align__(16) float g_h0[Tn*HB];          // [t][d][b]
__device__ __align__(16) float g_h1[Tn*HB];
__device__ __align__(16) float g_h2[Tn*HB];
__device__ __align__(16) float g_w [Tn*NB];          // [t][n][b]
__device__ __align__(16) float g_xz[Tn*ZB];          // [t][col][b]
__device__ __align__(16) float g_xT[Tn*3*Bn];        // [t][dim][b]
__device__ unsigned g_barc[4];                       // monotone barrier counters

// ---------------- fp32x2 helpers -----------------------------------------
__device__ __forceinline__ void fma2(ull &acc, ull a, ull b) {
    asm("fma.rn.f32x2 %0, %1, %2, %0;" : "+l"(acc) : "l"(a), "l"(b));
}
__device__ __forceinline__ ull dup2(float w) {
    ull r; asm("mov.b64 %0, {%1, %1};" : "=l"(r) : "f"(w)); return r;
}
__device__ __forceinline__ void unpack2(ull v, float &lo, float &hi) {
    asm("mov.b64 {%0, %1}, %2;" : "=f"(lo), "=f"(hi) : "l"(v));
}

// 8 cols x 4 batches accumulate: acc[2j]=(b0,b1), acc[2j+1]=(b2,b3) for col j
__device__ __forceinline__ void mac8(ull* acc, ulonglong2 in, float4 w0, float4 w1) {
    fma2(acc[0],  in.x, dup2(w0.x)); fma2(acc[1],  in.y, dup2(w0.x));
    fma2(acc[2],  in.x, dup2(w0.y)); fma2(acc[3],  in.y, dup2(w0.y));
    fma2(acc[4],  in.x, dup2(w0.z)); fma2(acc[5],  in.y, dup2(w0.z));
    fma2(acc[6],  in.x, dup2(w0.w)); fma2(acc[7],  in.y, dup2(w0.w));
    fma2(acc[8],  in.x, dup2(w1.x)); fma2(acc[9],  in.y, dup2(w1.x));
    fma2(acc[10], in.x, dup2(w1.y)); fma2(acc[11], in.y, dup2(w1.y));
    fma2(acc[12], in.x, dup2(w1.z)); fma2(acc[13], in.y, dup2(w1.z));
    fma2(acc[14], in.x, dup2(w1.w)); fma2(acc[15], in.y, dup2(w1.w));
}

// 32 distinct rows per warp, 8-deep LDG prefetch.
// gp: row0 input (+bg*4), wp: sW row0 weights (+ch*8)
__device__ __forceinline__ void gemm_rows32(ull* acc, const float* __restrict__ gp,
                                            const float* __restrict__ wp) {
    ulonglong2 ib[8];
    #pragma unroll
    for (int i = 0; i < 8; ++i)
        ib[i] = *reinterpret_cast<const ulonglong2*>(gp + (size_t)i*64);
    #pragma unroll
    for (int c = 0; c < 4; ++c) {
        #pragma unroll
        for (int i = 0; i < 8; ++i) {
            int r = c*8 + i;
            float4 w0 = *reinterpret_cast<const float4*>(wp + r*16);
            float4 w1 = *reinterpret_cast<const float4*>(wp + r*16 + 4);
            ulonglong2 in = ib[i];
            if (c < 3)
                ib[i] = *reinterpret_cast<const ulonglong2*>(gp + (size_t)(r+8)*64);
            mac8(acc, in, w0, w1);
        }
    }
}

// n extra rows (no pipeline; n small)
__device__ __forceinline__ void gemm_rowsN(ull* acc, const float* __restrict__ gp,
                                           const float* __restrict__ wp, int n) {
    #pragma unroll 4
    for (int r = 0; r < n; ++r) {
        ulonglong2 in = *reinterpret_cast<const ulonglong2*>(gp + (size_t)r*64);
        float4 w0 = *reinterpret_cast<const float4*>(wp + r*16);
        float4 w1 = *reinterpret_cast<const float4*>(wp + r*16 + 4);
        mac8(acc, in, w0, w1);
    }
}

// sP layout: [slice 16][col 16][b 64]
__device__ __forceinline__ void store_partials(float* sP, int warp, int ch, int bg,
                                               const ull* acc) {
    float* pp = sP + warp*1024 + (ch*8)*64 + bg*4;
    #pragma unroll
    for (int j = 0; j < 8; ++j)
        *reinterpret_cast<ulonglong2*>(pp + j*64) = make_ulonglong2(acc[2*j], acc[2*j+1]);
}

// reduce 16 slices for gate column col, batch b (4-way split chains)
__device__ __forceinline__ float reduce16(const float* sP, int col, int b) {
    const float* p = sP + col*64 + b;
    float s0 = p[0]       + p[1024];
    float s1 = p[2*1024]  + p[3*1024];
    float s2 = p[4*1024]  + p[5*1024];
    float s3 = p[6*1024]  + p[7*1024];
    s0 += p[8*1024]  + p[9*1024];
    s1 += p[10*1024] + p[11*1024];
    s2 += p[12*1024] + p[13*1024];
    s3 += p[14*1024] + p[15*1024];
    return (s0 + s1) + (s2 + s3);
}

// fast gates (~1e-6 rel err)
__device__ __forceinline__ float sigf2(float x) {
    return __fdividef(1.f, 1.f + __expf(-x));
}
__device__ __forceinline__ float tanhf2(float x) {
    return 1.f - __fdividef(2.f, __expf(2.f*x) + 1.f);
}

// ---------------- release/acquire barrier primitives ---------------------
__device__ __forceinline__ void bar_arrive(int slot) {
    asm volatile("red.release.gpu.global.add.u32 [%0], 1;"
                 :: "l"(g_barc + slot) : "memory");
}
__device__ __forceinline__ void bar_wait_ge(int slot, unsigned target) {
    unsigned v;
    do {
        asm volatile("ld.acquire.gpu.global.u32 %0, [%1];"
                     : "=r"(v) : "l"(g_barc + slot) : "memory");
    } while (v < target);
}
__device__ __forceinline__ void bar_epoch(int slot, unsigned target) {
    __syncthreads();
    if (threadIdx.x == 0) { bar_arrive(slot); bar_wait_ge(slot, target); }
    __syncthreads();
}

// ---------------- init: barrier vars + stroke transpose ------------------
__global__ void k_init(const float* __restrict__ strokes) {
    int i = blockIdx.x * blockDim.x + threadIdx.x;
    int stride = gridDim.x * blockDim.x;
    for (int j = i; j < Tn*3*Bn; j += stride) {
        int t = j / 192, rem = j % 192, dim = rem / 64, b = rem & 63;
        g_xT[j] = strokes[b*(Tn*3) + t*3 + dim];
    }
    if (i < 4) g_barc[i] = 0u;
}

// =========================================================================
// Layer-0 scan + attention.  128 CTAs x 512 thr persistent.
// warp w: h rows [32w,32w+32), w rows [512+4w,512+4w+4), warp15 adds x(3).
// lane: bg = lane&15 (4 batches), ch = lane>>4 (8 cols).
// slot0 = "h[t] ready" (S1), slot1 = "w[t] ready" (S2).
// =========================================================================
__global__ void __launch_bounds__(512, 1)
k_scan0(const float* __restrict__ trans,
        const float* __restrict__ W0, const float* __restrict__ R0,
        const float* __restrict__ b0, const float* __restrict__ Wd,
        const float* __restrict__ bd, float* __restrict__ attOut)
{
    extern __shared__ float sm[];
    float* sW = sm;                  // 579*16 = 9264
    float* sP = sm + 9264;           // 16*16*64 = 16384
    __shared__ float sb[16];
    __shared__ float sPart[16*32];
    __shared__ float sy[32];
    __shared__ float skap[10];
    __shared__ float swf[72];

    const int tid  = threadIdx.x;
    const int lane = tid & 31;
    const int warp = tid >> 5;
    const int bg   = lane & 15;
    const int ch   = lane >> 4;
    const int u0   = blockIdx.x * 4;
    const int bR   = tid & 63;       // reduce: batch
    const int uuR  = tid >> 6;       // reduce: unit (tid<256)

    // stage weights (rows: 0..511 R0, 512..575 W0[3..66], 576..578 W0[0..2])
    for (int idx = tid; idx < 9264; idx += 512) {
        int r = idx >> 4, c = idx & 15;
        int col = (c & 3) * 512 + u0 + (c >> 2);
        float v;
        if (r < 512)      v = R0[r*G4H + col];
        else if (r < 576) v = W0[(3 + r - 512)*G4H + col];
        else              v = W0[(r - 576)*G4H + col];
        sW[idx] = v;
    }
    if (tid < 16) sb[tid] = b0[(tid & 3) * 512 + u0 + (tid >> 2)];
    if (tid < 10) skap[tid] = 0.f;
    __syncthreads();

    float creg = 0.f;

    for (int t = 0; t < Tn; ++t) {
        ull acc[16];
        #pragma unroll
        for (int i = 0; i < 16; ++i) acc[i] = 0ull;

        // h rows (h[t-1] guaranteed by S1 of prev step)
        if (t > 0)
            gemm_rows32(acc, g_h0 + (size_t)(t-1)*HB + (warp*32)*64 + bg*4,
                        sW + (warp*32)*16 + ch*8);
        // x rows (3, warp 15)
        if (warp == 15)
            gemm_rowsN(acc, g_xT + (size_t)t*192 + bg*4, sW + 576*16 + ch*8, 3);
        // wait S2: w[t-1] ready
        if (tid == 0) bar_wait_ge(1, (unsigned)t * NCTA);
        __syncthreads();
        // w rows (4 per warp)
        if (t > 0)
            gemm_rowsN(acc, g_w + (size_t)(t-1)*NB + (warp*4)*64 + bg*4,
                       sW + (512 + warp*4)*16 + ch*8, 4);

        store_partials(sP, warp, ch, bg, acc);
        __syncthreads();
        if (tid < 256) {
            float z[4];
            #pragma unroll
            for (int g = 0; g < 4; ++g)
                z[g] = sb[uuR*4 + g] + reduce16(sP, uuR*4 + g, bR);
            float c2 = sigf2(z[1])*creg + sigf2(z[0])*tanhf2(z[2]);
            creg = c2;
            g_h0[(size_t)t*HB + (u0+uuR)*64 + bR] = sigf2(z[3])*tanhf2(c2);
        }
        // S1: h[t] ready everywhere
        bar_epoch(0, (unsigned)(t+1) * NCTA);

        // attention on CTAs 0..63; others arrive S2 immediately and proceed
        if (blockIdx.x < Bn) {
            const int b = blockIdx.x;
            const float* h2p = g_h0 + (size_t)t*HB;
            int cc = tid & 31, seg = tid >> 5;
            if (cc < 30) {
                int dbase = seg * 32;
                float part = 0.f;
                #pragma unroll 8
                for (int d = 0; d < 32; ++d)
                    part += h2p[(dbase + d)*64 + b] * Wd[(dbase + d)*30 + cc];
                sPart[seg*32 + cc] = part;
            }
            __syncthreads();
            if (tid < 30) {
                float y = bd[tid];
                #pragma unroll
                for (int s = 0; s < 16; ++s) y += sPart[s*32 + tid];
                sy[tid] = expf(y);
            }
            __syncthreads();
            if (tid < Kn) skap[tid] += sy[20 + tid];
            __syncthreads();
            if (tid < Un + 1) {
                float s = 0.f;
                #pragma unroll
                for (int k = 0; k < Kn; ++k) {
                    float dd  = skap[k] - (float)(tid + 1);
                    float arg = -sy[10 + k] * dd * dd;
                    if (arg < EXP_LO) arg = EXP_LO;   // Eigen pexp clamp
                    s += sy[k] * expf(arg);
                }
                swf[tid] = s;
            }
            __syncthreads();
            if (tid < Nn) {
                float acc2 = 0.f;
                #pragma unroll 8
                for (int u = 0; u < Un; ++u)
                    acc2 += swf[u] * trans[b*(Un*Nn) + u*Nn + tid];
                g_w[(size_t)t*NB + tid*64 + b] = acc2;
            }
            if (tid == 0) {
                float best = swf[0]; int bi = 0;
                for (int u = 1; u < Un + 1; ++u)
                    if (swf[u] > best) { best = swf[u]; bi = u; }
                attOut[b*Tn + t] = (float)bi;
            }
            __syncthreads();
            if (tid == 0) bar_arrive(1);   // S2: w[t] done (release publishes w)
        } else {
            if (tid == 0) bar_arrive(1);   // S2 arrive (vacuous)
        }
    }
}

// =========================================================================
// xz projection GEMM for layers 1/2: xz[t][col][b] = x1[t]@W + b
// grid (128 colgroups, 8 t-slices) x 512 thr
// =========================================================================
__global__ void __launch_bounds__(512, 1)
k_xz(const float* __restrict__ W, const float* __restrict__ bias, int sel)
{
    extern __shared__ float sm[];
    float* sW = sm;                  // 9264
    float* sP = sm + 9264;           // 16384
    __shared__ float sb[16];

    const float* hin = (sel == 1) ? g_h0 : g_h1;
    const int tid  = threadIdx.x;
    const int lane = tid & 31;
    const int warp = tid >> 5;
    const int bg   = lane & 15;
    const int ch   = lane >> 4;
    const int u0   = blockIdx.x * 4;

    for (int idx = tid; idx < 9264; idx += 512) {
        int r = idx >> 4, c = idx & 15;
        sW[idx] = W[r*G4H + (c & 3) * 512 + u0 + (c >> 2)];
    }
    if (tid < 16) sb[tid] = bias[(tid & 3) * 512 + u0 + (tid >> 2)];
    __syncthreads();

    const int t0 = blockIdx.y * (Tn / 8);
    const int t1 = t0 + (Tn / 8);
    for (int t = t0; t < t1; ++t) {
        ull acc[16];
        #pragma unroll
        for (int i = 0; i < 16; ++i) acc[i] = 0ull;

        gemm_rows32(acc, hin + (size_t)t*HB + (warp*32)*64 + bg*4,
                    sW + (warp*32)*16 + ch*8);
        gemm_rowsN(acc, g_w + (size_t)t*NB + (warp*4)*64 + bg*4,
                   sW + (512 + warp*4)*16 + ch*8, 4);
        if (warp == 15)
            gemm_rowsN(acc, g_xT + (size_t)t*192 + bg*4, sW + 576*16 + ch*8, 3);

        store_partials(sP, warp, ch, bg, acc);
        __syncthreads();
        if (tid < 256) {
            int b = tid & 63, uu = tid >> 6;
            #pragma unroll
            for (int g = 0; g < 4; ++g) {
                int c = uu*4 + g;
                float s = sb[c] + reduce16(sP, c, b);
                int col = (c & 3) * 512 + u0 + (c >> 2);
                g_xz[(size_t)t*ZB + col*64 + b] = s;
            }
        }
        __syncthreads();
    }
}

// =========================================================================
// Layers 1/2 recurrent scan: z = xz[t] + h_{t-1} @ R ; LSTM pointwise.
// =========================================================================
__global__ void __launch_bounds__(512, 1)
k_scan12(const float* __restrict__ R, int sel)
{
    extern __shared__ float sm[];
    float* sW = sm;                  // 512*16 = 8192
    float* sP = sm + 8192;           // 16384

    float* hseq = (sel == 1) ? g_h1 : g_h2;
    const int slot = sel + 1;        // 2 or 3
    const int tid  = threadIdx.x;
    const int lane = tid & 31;
    const int warp = tid >> 5;
    const int bg   = lane & 15;
    const int ch   = lane >> 4;
    const int u0   = blockIdx.x * 4;
    const int bR   = tid & 63;
    const int uuR  = tid >> 6;

    for (int idx = tid; idx < 8192; idx += 512) {
        int r = idx >> 4, c = idx & 15;
        sW[idx] = R[r*G4H + (c & 3) * 512 + u0 + (c >> 2)];
    }
    float creg = 0.f;
    __syncthreads();

    for (int t = 0; t < Tn; ++t) {
        // prefetch this step's xz for the reduce threads (hides L2 latency)
        float xzv[4];
        if (tid < 256) {
            #pragma unroll
            for (int g = 0; g < 4; ++g)
                xzv[g] = g_xz[(size_t)t*ZB + (g*512 + u0 + uuR)*64 + bR];
        }
        ull acc[16];
        #pragma unroll
        for (int i = 0; i < 16; ++i) acc[i] = 0ull;
        if (t > 0)
            gemm_rows32(acc, hseq + (size_t)(t-1)*HB + (warp*32)*64 + bg*4,
                        sW + (warp*32)*16 + ch*8);
        store_partials(sP, warp, ch, bg, acc);
        __syncthreads();
        if (tid < 256) {
            float z[4];
            #pragma unroll
            for (int g = 0; g < 4; ++g)
                z[g] = xzv[g] + reduce16(sP, uuR*4 + g, bR);
            float c2 = sigf2(z[1])*creg + sigf2(z[0])*tanhf2(z[2]);
            creg = c2;
            hseq[(size_t)t*HB + (u0+uuR)*64 + bR] = sigf2(z[3])*tanhf2(c2);
        }
        bar_epoch(slot, (unsigned)(t+1) * NCTA);
    }
}

// =========================================================================
// Output GEMM: out[b][t][o] = [h0,h1,h2][t] @ Wo + bo   (grid = 800 CTAs)
// =========================================================================
__global__ void __launch_bounds__(256)
k_out(const float* __restrict__ Wo, const float* __restrict__ bo,
      float* __restrict__ out)
{
    const int t = blockIdx.x;
    const int tid = threadIdx.x;
    const int c = tid & 127;
    const int bh = tid >> 7;            // 0/1: batches bh*32..bh*32+31
    if (c >= On) return;

    ull acc[16];
    ull bias2 = dup2(bo[c]);
    #pragma unroll
    for (int i = 0; i < 16; ++i) acc[i] = bias2;

    #pragma unroll
    for (int l = 0; l < 3; ++l) {
        const float* hp = (l == 0 ? g_h0 : l == 1 ? g_h1 : g_h2) + (size_t)t*HB;
        const float* wp = Wo + (l*512)*On + c;
        #pragma unroll 2
        for (int d = 0; d < 512; ++d) {
            ull wv = dup2(wp[d*On]);
            const ulonglong2* h4 = reinterpret_cast<const ulonglong2*>(hp + d*64 + bh*32);
            #pragma unroll
            for (int q = 0; q < 8; ++q) {
                ulonglong2 hv = h4[q];
                fma2(acc[2*q],   hv.x, wv);
                fma2(acc[2*q+1], hv.y, wv);
            }
        }
    }
    #pragma unroll
    for (int i = 0; i < 16; ++i) {
        float lo, hi; unpack2(acc[i], lo, hi);
        int b = bh*32 + 2*i;
        out[(size_t)b     *(Tn*On) + t*On + c] = lo;
        out[(size_t)(b+1) *(Tn*On) + t*On + c] = hi;
    }
}

// =========================================================================
extern "C" void kernel_launch(void* const* d_in, const int* in_sizes, int n_in,
                              void* d_out, int out_size)
{
    const float* strokes = (const float*)d_in[0];
    const float* trans   = (const float*)d_in[1];
    const float* W0      = (const float*)d_in[2];
    const float* R0      = (const float*)d_in[3];
    const float* b0      = (const float*)d_in[4];
    const float* Wd      = (const float*)d_in[5];
    const float* bd      = (const float*)d_in[6];
    const float* W1      = (const float*)d_in[7];
    const float* R1      = (const float*)d_in[8];
    const float* b1      = (const float*)d_in[9];
    const float* W2      = (const float*)d_in[10];
    const float* R2      = (const float*)d_in[11];
    const float* b2      = (const float*)d_in[12];
    const float* Wo      = (const float*)d_in[13];
    const float* bo      = (const float*)d_in[14];

    float* out = (float*)d_out;
    float* att = out + (size_t)Bn * Tn * On;

    const int smem_scan0  = (9264 + 16384) * 4;   // 102592
    const int smem_xz     = (9264 + 16384) * 4;   // 102592
    const int smem_scan12 = (8192 + 16384) * 4;   // 98304
    cudaFuncSetAttribute(k_scan0,  cudaFuncAttributeMaxDynamicSharedMemorySize, smem_scan0);
    cudaFuncSetAttribute(k_xz,     cudaFuncAttributeMaxDynamicSharedMemorySize, smem_xz);
    cudaFuncSetAttribute(k_scan12, cudaFuncAttributeMaxDynamicSharedMemorySize, smem_scan12);

    k_init<<<256, 256>>>(strokes);
    k_scan0<<<NCTA, 512, smem_scan0>>>(trans, W0, R0, b0, Wd, bd, att);
    k_xz<<<dim3(NCTA, 8), 512, smem_xz>>>(W1, b1, 1);
    k_scan12<<<NCTA, 512, smem_scan12>>>(R1, 1);
    k_xz<<<dim3(NCTA, 8), 512, smem_xz>>>(W2, b2, 2);
    k_scan12<<<NCTA, 512, smem_scan12>>>(R2, 2);
    k_out<<<Tn, 256>>>(Wo, bo, out);
}

// round 8
// speedup vs baseline: 5.7285x; 1.1617x over previous
#include <cuda_runtime.h>
#include <math.h>

#define Bn 64
#define Tn 800
#define Un 64
#define Nn 64
#define Kn 10
#define Hn 512
#define On 121
#define G4H 2048
#define HB (Hn*Bn)      /* 32768 */
#define NB (Nn*Bn)      /* 4096  */
#define NCTA 128

typedef unsigned long long ull;

// Eigen/XLA-CPU pexp clamps its argument at ln(2^-126); replicate so the
// underflow tail ties bit-exactly (argmax -> 0) like the reference.
#define EXP_LO (-87.33654f)

// ---------------- device scratch (static, no allocations) ----------------
__device__ __align__(16) float g_h0[Tn*HB];          // [t][d][b]
__device__ __align__(16) float g_h1[Tn*HB];
__device__ __align__(16) float g_h2[Tn*HB];
__device__ __align__(16) float g_w [Tn*NB];          // [t][n][b]
__device__ __align__(16) float g_xT[Tn*3*Bn];        // [t][dim][b]
__device__ unsigned g_barc[4];                       // monotone barrier counters

// ---------------- fp32x2 helpers -----------------------------------------
__device__ __forceinline__ void fma2(ull &acc, ull a, ull b) {
    asm("fma.rn.f32x2 %0, %1, %2, %0;" : "+l"(acc) : "l"(a), "l"(b));
}
__device__ __forceinline__ ull dup2(float w) {
    ull r; asm("mov.b64 %0, {%1, %1};" : "=l"(r) : "f"(w)); return r;
}
__device__ __forceinline__ void unpack2(ull v, float &lo, float &hi) {
    asm("mov.b64 {%0, %1}, %2;" : "=f"(lo), "=f"(hi) : "l"(v));
}

// 8 cols x 4 batches accumulate: acc[2j]=(b0,b1), acc[2j+1]=(b2,b3) for col j
__device__ __forceinline__ void mac8(ull* acc, ulonglong2 in, float4 w0, float4 w1) {
    fma2(acc[0],  in.x, dup2(w0.x)); fma2(acc[1],  in.y, dup2(w0.x));
    fma2(acc[2],  in.x, dup2(w0.y)); fma2(acc[3],  in.y, dup2(w0.y));
    fma2(acc[4],  in.x, dup2(w0.z)); fma2(acc[5],  in.y, dup2(w0.z));
    fma2(acc[6],  in.x, dup2(w0.w)); fma2(acc[7],  in.y, dup2(w0.w));
    fma2(acc[8],  in.x, dup2(w1.x)); fma2(acc[9],  in.y, dup2(w1.x));
    fma2(acc[10], in.x, dup2(w1.y)); fma2(acc[11], in.y, dup2(w1.y));
    fma2(acc[12], in.x, dup2(w1.z)); fma2(acc[13], in.y, dup2(w1.z));
    fma2(acc[14], in.x, dup2(w1.w)); fma2(acc[15], in.y, dup2(w1.w));
}

// 32 distinct rows per warp, 8-deep LDG prefetch.
__device__ __forceinline__ void gemm_rows32(ull* acc, const float* __restrict__ gp,
                                            const float* __restrict__ wp) {
    ulonglong2 ib[8];
    #pragma unroll
    for (int i = 0; i < 8; ++i)
        ib[i] = *reinterpret_cast<const ulonglong2*>(gp + (size_t)i*64);
    #pragma unroll
    for (int c = 0; c < 4; ++c) {
        #pragma unroll
        for (int i = 0; i < 8; ++i) {
            int r = c*8 + i;
            float4 w0 = *reinterpret_cast<const float4*>(wp + r*16);
            float4 w1 = *reinterpret_cast<const float4*>(wp + r*16 + 4);
            ulonglong2 in = ib[i];
            if (c < 3)
                ib[i] = *reinterpret_cast<const ulonglong2*>(gp + (size_t)(r+8)*64);
            mac8(acc, in, w0, w1);
        }
    }
}

__device__ __forceinline__ void gemm_rowsN(ull* acc, const float* __restrict__ gp,
                                           const float* __restrict__ wp, int n) {
    #pragma unroll 4
    for (int r = 0; r < n; ++r) {
        ulonglong2 in = *reinterpret_cast<const ulonglong2*>(gp + (size_t)r*64);
        float4 w0 = *reinterpret_cast<const float4*>(wp + r*16);
        float4 w1 = *reinterpret_cast<const float4*>(wp + r*16 + 4);
        mac8(acc, in, w0, w1);
    }
}

// sP layout: [slice 16][col 16][b 64]
__device__ __forceinline__ void store_partials(float* sP, int warp, int ch, int bg,
                                               const ull* acc) {
    float* pp = sP + warp*1024 + (ch*8)*64 + bg*4;
    #pragma unroll
    for (int j = 0; j < 8; ++j)
        *reinterpret_cast<ulonglong2*>(pp + j*64) = make_ulonglong2(acc[2*j], acc[2*j+1]);
}

__device__ __forceinline__ float reduce16(const float* sP, int col, int b) {
    const float* p = sP + col*64 + b;
    float s0 = p[0]       + p[1024];
    float s1 = p[2*1024]  + p[3*1024];
    float s2 = p[4*1024]  + p[5*1024];
    float s3 = p[6*1024]  + p[7*1024];
    s0 += p[8*1024]  + p[9*1024];
    s1 += p[10*1024] + p[11*1024];
    s2 += p[12*1024] + p[13*1024];
    s3 += p[14*1024] + p[15*1024];
    return (s0 + s1) + (s2 + s3);
}

// fast gates (~1e-6 rel err)
__device__ __forceinline__ float sigf2(float x) {
    return __fdividef(1.f, 1.f + __expf(-x));
}
__device__ __forceinline__ float tanhf2(float x) {
    return 1.f - __fdividef(2.f, __expf(2.f*x) + 1.f);
}

// ---------------- release/acquire barrier primitives ---------------------
__device__ __forceinline__ void bar_arrive(int slot) {
    asm volatile("red.release.gpu.global.add.u32 [%0], 1;"
                 :: "l"(g_barc + slot) : "memory");
}
__device__ __forceinline__ void bar_wait_ge(int slot, unsigned target) {
    unsigned v;
    do {
        asm volatile("ld.acquire.gpu.global.u32 %0, [%1];"
                     : "=r"(v) : "l"(g_barc + slot) : "memory");
    } while (v < target);
}

// ---------------- init: barrier vars + stroke transpose ------------------
__global__ void k_init(const float* __restrict__ strokes) {
    int i = blockIdx.x * blockDim.x + threadIdx.x;
    int stride = gridDim.x * blockDim.x;
    for (int j = i; j < Tn*3*Bn; j += stride) {
        int t = j / 192, rem = j % 192, dim = rem / 64, b = rem & 63;
        g_xT[j] = strokes[b*(Tn*3) + t*3 + dim];
    }
    if (i < 4) g_barc[i] = 0u;
}

// =========================================================================
// Layer-0 scan + attention.  128 CTAs x 512 thr persistent.
// warp w: h rows [32w,32w+32), w rows [512+4w,+4), warp15 adds x(3).
// slot0 = "h[t] ready" (S1), slot1 = "w[t] ready" (S2).
// Attention CTAs (0..63) cache Wd + their trans[b] slice in SMEM.
// =========================================================================
__global__ void __launch_bounds__(512, 1)
k_scan0(const float* __restrict__ trans,
        const float* __restrict__ W0, const float* __restrict__ R0,
        const float* __restrict__ b0, const float* __restrict__ Wd,
        const float* __restrict__ bd, float* __restrict__ attOut)
{
    extern __shared__ float sm[];
    float* sW  = sm;                      // 579*16  = 9264
    float* sP  = sm + 9264;               // 16*16*64 = 16384
    float* sWd = sm + 9264 + 16384;       // 512*30 = 15360
    float* sTr = sm + 9264 + 16384 + 15360; // 64*64 = 4096
    __shared__ float sb[16];
    __shared__ float sPart[16*32];
    __shared__ float sy[32];
    __shared__ float skap[10];
    __shared__ float swf[72];

    const int tid  = threadIdx.x;
    const int lane = tid & 31;
    const int warp = tid >> 5;
    const int bg   = lane & 15;
    const int ch   = lane >> 4;
    const int u0   = blockIdx.x * 4;
    const int bR   = tid & 63;
    const int uuR  = tid >> 6;
    const bool isAtt = (blockIdx.x < Bn);

    for (int idx = tid; idx < 9264; idx += 512) {
        int r = idx >> 4, c = idx & 15;
        int col = (c & 3) * 512 + u0 + (c >> 2);
        float v;
        if (r < 512)      v = R0[r*G4H + col];
        else if (r < 576) v = W0[(3 + r - 512)*G4H + col];
        else              v = W0[(r - 576)*G4H + col];
        sW[idx] = v;
    }
    if (isAtt) {
        for (int idx = tid; idx < 512*30; idx += 512) sWd[idx] = Wd[idx];
        const int b = blockIdx.x;
        for (int idx = tid; idx < 64*64; idx += 512)
            sTr[idx] = trans[b*(Un*Nn) + idx];
    }
    if (tid < 16) sb[tid] = b0[(tid & 3) * 512 + u0 + (tid >> 2)];
    if (tid < 10) skap[tid] = 0.f;
    __syncthreads();

    float creg = 0.f;

    for (int t = 0; t < Tn; ++t) {
        ull acc[16];
        #pragma unroll
        for (int i = 0; i < 16; ++i) acc[i] = 0ull;

        if (t > 0)
            gemm_rows32(acc, g_h0 + (size_t)(t-1)*HB + (warp*32)*64 + bg*4,
                        sW + (warp*32)*16 + ch*8);
        if (warp == 15)
            gemm_rowsN(acc, g_xT + (size_t)t*192 + bg*4, sW + 576*16 + ch*8, 3);
        // wait S2: w[t-1] ready
        if (tid == 0) bar_wait_ge(1, (unsigned)t * NCTA);
        __syncthreads();
        if (t > 0)
            gemm_rowsN(acc, g_w + (size_t)(t-1)*NB + (warp*4)*64 + bg*4,
                       sW + (512 + warp*4)*16 + ch*8, 4);

        store_partials(sP, warp, ch, bg, acc);
        __syncthreads();
        if (tid < 256) {
            float z[4];
            #pragma unroll
            for (int g = 0; g < 4; ++g)
                z[g] = sb[uuR*4 + g] + reduce16(sP, uuR*4 + g, bR);
            float c2 = sigf2(z[1])*creg + sigf2(z[0])*tanhf2(z[2]);
            creg = c2;
            g_h0[(size_t)t*HB + (u0+uuR)*64 + bR] = sigf2(z[3])*tanhf2(c2);
        }
        // S1: h[t] ready everywhere
        __syncthreads();
        if (tid == 0) { bar_arrive(0); bar_wait_ge(0, (unsigned)(t+1) * NCTA); }
        __syncthreads();

        // attention on CTAs 0..63
        if (isAtt) {
            const int b = blockIdx.x;
            const float* h2p = g_h0 + (size_t)t*HB;
            int cc = tid & 31, seg = tid >> 5;
            if (cc < 30) {
                int dbase = seg * 32;
                float part = 0.f;
                #pragma unroll 8
                for (int d = 0; d < 32; ++d)
                    part += h2p[(dbase + d)*64 + b] * sWd[(dbase + d)*30 + cc];
                sPart[seg*32 + cc] = part;
            }
            __syncthreads();
            if (tid < 30) {
                float y = bd[tid];
                #pragma unroll
                for (int s = 0; s < 16; ++s) y += sPart[s*32 + tid];
                sy[tid] = expf(y);
            }
            __syncthreads();
            if (tid < Kn) skap[tid] += sy[20 + tid];
            __syncthreads();
            if (tid < Un + 1) {
                float s = 0.f;
                #pragma unroll
                for (int k = 0; k < Kn; ++k) {
                    float dd  = skap[k] - (float)(tid + 1);
                    float arg = -sy[10 + k] * dd * dd;
                    if (arg < EXP_LO) arg = EXP_LO;   // Eigen pexp clamp
                    s += sy[k] * expf(arg);
                }
                swf[tid] = s;
            }
            __syncthreads();
            if (tid < Nn) {
                float acc2 = 0.f;
                #pragma unroll 8
                for (int u = 0; u < Un; ++u)
                    acc2 += swf[u] * sTr[u*64 + tid];
                g_w[(size_t)t*NB + tid*64 + b] = acc2;
            }
            if (tid == 0) {
                float best = swf[0]; int bi = 0;
                for (int u = 1; u < Un + 1; ++u)
                    if (swf[u] > best) { best = swf[u]; bi = u; }
                attOut[b*Tn + t] = (float)bi;
            }
            __syncthreads();
            if (tid == 0) bar_arrive(1);   // S2: w[t] done
        } else {
            if (tid == 0) bar_arrive(1);
        }
    }
}

// =========================================================================
// Fused layers 1/2 scan: z = [h_in, w, x]@Wff + h[t-1]@R + b ; LSTM.
// The feedforward GEMM of step t+1 runs between barrier arrive and wait,
// hiding barrier latency + straggler spread behind independent FMAs.
// sW rows: [0..511]=R, [512..1023]=W h-part, [1024..1087]=W w-part,
//          [1088..1090]=W x-part.
// =========================================================================
__global__ void __launch_bounds__(512, 1)
k_scan12f(const float* __restrict__ R, const float* __restrict__ W,
          const float* __restrict__ bias, int sel)
{
    extern __shared__ float sm[];
    float* sW = sm;                  // 1091*16 = 17456
    float* sP = sm + 17456;          // 16384
    __shared__ float sb[16];

    const float* hin = (sel == 1) ? g_h0 : g_h1;
    float* hseq      = (sel == 1) ? g_h1 : g_h2;
    const int slot = sel + 1;        // 2 or 3
    const int tid  = threadIdx.x;
    const int lane = tid & 31;
    const int warp = tid >> 5;
    const int bg   = lane & 15;
    const int ch   = lane >> 4;
    const int u0   = blockIdx.x * 4;
    const int bR   = tid & 63;
    const int uuR  = tid >> 6;

    for (int idx = tid; idx < 1091*16; idx += 512) {
        int r = idx >> 4, c = idx & 15;
        int col = (c & 3) * 512 + u0 + (c >> 2);
        float v;
        if (r < 512)       v = R[r*G4H + col];
        else if (r < 1024) v = W[(r - 512)*G4H + col];
        else if (r < 1088) v = W[(512 + r - 1024)*G4H + col];
        else               v = W[(576 + r - 1088)*G4H + col];
        sW[idx] = v;
    }
    if (tid < 16) sb[tid] = bias[(tid & 3) * 512 + u0 + (tid >> 2)];
    float creg = 0.f;
    __syncthreads();

    ull acc[16];
    #pragma unroll
    for (int i = 0; i < 16; ++i) acc[i] = 0ull;
    // feedforward part of step 0
    gemm_rows32(acc, hin + (size_t)0*HB + (warp*32)*64 + bg*4,
                sW + (512 + warp*32)*16 + ch*8);
    gemm_rowsN(acc, g_w + (size_t)0*NB + (warp*4)*64 + bg*4,
               sW + (1024 + warp*4)*16 + ch*8, 4);
    if (warp == 15)
        gemm_rowsN(acc, g_xT + (size_t)0*192 + bg*4, sW + 1088*16 + ch*8, 3);

    for (int t = 0; t < Tn; ++t) {
        // recurrent part: h[t-1] @ R (h[t-1] published by prev-iter barrier)
        if (t > 0)
            gemm_rows32(acc, hseq + (size_t)(t-1)*HB + (warp*32)*64 + bg*4,
                        sW + (warp*32)*16 + ch*8);

        store_partials(sP, warp, ch, bg, acc);
        __syncthreads();
        if (tid < 256) {
            float z[4];
            #pragma unroll
            for (int g = 0; g < 4; ++g)
                z[g] = sb[uuR*4 + g] + reduce16(sP, uuR*4 + g, bR);
            float c2 = sigf2(z[1])*creg + sigf2(z[0])*tanhf2(z[2]);
            creg = c2;
            hseq[(size_t)t*HB + (u0+uuR)*64 + bR] = sigf2(z[3])*tanhf2(c2);
        }
        __syncthreads();
        if (tid == 0) bar_arrive(slot);

        // hide barrier latency behind next step's feedforward GEMM
        #pragma unroll
        for (int i = 0; i < 16; ++i) acc[i] = 0ull;
        if (t < Tn - 1) {
            gemm_rows32(acc, hin + (size_t)(t+1)*HB + (warp*32)*64 + bg*4,
                        sW + (512 + warp*32)*16 + ch*8);
            gemm_rowsN(acc, g_w + (size_t)(t+1)*NB + (warp*4)*64 + bg*4,
                       sW + (1024 + warp*4)*16 + ch*8, 4);
            if (warp == 15)
                gemm_rowsN(acc, g_xT + (size_t)(t+1)*192 + bg*4,
                           sW + 1088*16 + ch*8, 3);
        }
        if (tid == 0) bar_wait_ge(slot, (unsigned)(t+1) * NCTA);
        __syncthreads();
    }
}

// =========================================================================
// Output GEMM: out[b][t][o] = [h0,h1,h2][t] @ Wo + bo   (grid = 800 CTAs)
// =========================================================================
__global__ void __launch_bounds__(256)
k_out(const float* __restrict__ Wo, const float* __restrict__ bo,
      float* __restrict__ out)
{
    const int t = blockIdx.x;
    const int tid = threadIdx.x;
    const int c = tid & 127;
    const int bh = tid >> 7;
    if (c >= On) return;

    ull acc[16];
    ull bias2 = dup2(bo[c]);
    #pragma unroll
    for (int i = 0; i < 16; ++i) acc[i] = bias2;

    #pragma unroll
    for (int l = 0; l < 3; ++l) {
        const float* hp = (l == 0 ? g_h0 : l == 1 ? g_h1 : g_h2) + (size_t)t*HB;
        const float* wp = Wo + (l*512)*On + c;
        #pragma unroll 2
        for (int d = 0; d < 512; ++d) {
            ull wv = dup2(wp[d*On]);
            const ulonglong2* h4 = reinterpret_cast<const ulonglong2*>(hp + d*64 + bh*32);
            #pragma unroll
            for (int q = 0; q < 8; ++q) {
                ulonglong2 hv = h4[q];
                fma2(acc[2*q],   hv.x, wv);
                fma2(acc[2*q+1], hv.y, wv);
            }
        }
    }
    #pragma unroll
    for (int i = 0; i < 16; ++i) {
        float lo, hi; unpack2(acc[i], lo, hi);
        int b = bh*32 + 2*i;
        out[(size_t)b     *(Tn*On) + t*On + c] = lo;
        out[(size_t)(b+1) *(Tn*On) + t*On + c] = hi;
    }
}

// =========================================================================
extern "C" void kernel_launch(void* const* d_in, const int* in_sizes, int n_in,
                              void* d_out, int out_size)
{
    const float* strokes = (const float*)d_in[0];
    const float* trans   = (const float*)d_in[1];
    const float* W0      = (const float*)d_in[2];
    const float* R0      = (const float*)d_in[3];
    const float* b0      = (const float*)d_in[4];
    const float* Wd      = (const float*)d_in[5];
    const float* bd      = (const float*)d_in[6];
    const float* W1      = (const float*)d_in[7];
    const float* R1      = (const float*)d_in[8];
    const float* b1      = (const float*)d_in[9];
    const float* W2      = (const float*)d_in[10];
    const float* R2      = (const float*)d_in[11];
    const float* b2      = (const float*)d_in[12];
    const float* Wo      = (const float*)d_in[13];
    const float* bo      = (const float*)d_in[14];

    float* out = (float*)d_out;
    float* att = out + (size_t)Bn * Tn * On;

    const int smem_scan0 = (9264 + 16384 + 15360 + 4096) * 4;  // 180416
    const int smem_s12f  = (17456 + 16384) * 4;                // 135360
    cudaFuncSetAttribute(k_scan0,   cudaFuncAttributeMaxDynamicSharedMemorySize, smem_scan0);
    cudaFuncSetAttribute(k_scan12f, cudaFuncAttributeMaxDynamicSharedMemorySize, smem_s12f);

    k_init<<<256, 256>>>(strokes);
    k_scan0<<<NCTA, 512, smem_scan0>>>(trans, W0, R0, b0, Wd, bd, att);
    k_scan12f<<<NCTA, 512, smem_s12f>>>(R1, W1, b1, 1);
    k_scan12f<<<NCTA, 512, smem_s12f>>>(R2, W2, b2, 2);
    k_out<<<Tn, 256>>>(Wo, bo, out);
}

// round 9
// speedup vs baseline: 5.8541x; 1.0219x over previous
#include <cuda_runtime.h>
#include <math.h>

#define Bn 64
#define Tn 800
#define Un 64
#define Nn 64
#define Kn 10
#define Hn 512
#define On 121
#define G4H 2048
#define HB (Hn*Bn)      /* 32768 */
#define NB (Nn*Bn)      /* 4096  */
#define NCTA 128

typedef unsigned long long ull;

// Eigen/XLA-CPU pexp clamps its argument at ln(2^-126); replicate so the
// underflow tail ties bit-exactly (argmax -> 0) like the reference.
#define EXP_LO (-87.33654f)

// ---------------- device scratch (static, no allocations) ----------------
__device__ __align__(16) float g_h0[Tn*HB];          // [t][d][b]
__device__ __align__(16) float g_h1[Tn*HB];
__device__ __align__(16) float g_h2[Tn*HB];
__device__ __align__(16) float g_w [Tn*NB];          // [t][n][b]
__device__ __align__(16) float g_xT[Tn*3*Bn];        // [t][dim][b]
__device__ unsigned g_barc[4];                       // monotone barrier counters

// ---------------- fp32x2 helpers -----------------------------------------
__device__ __forceinline__ void fma2(ull &acc, ull a, ull b) {
    asm("fma.rn.f32x2 %0, %1, %2, %0;" : "+l"(acc) : "l"(a), "l"(b));
}
__device__ __forceinline__ ull dup2(float w) {
    ull r; asm("mov.b64 %0, {%1, %1};" : "=l"(r) : "f"(w)); return r;
}
__device__ __forceinline__ void unpack2(ull v, float &lo, float &hi) {
    asm("mov.b64 {%0, %1}, %2;" : "=f"(lo), "=f"(hi) : "l"(v));
}

// 8 cols x 4 batches accumulate: acc[2j]=(b0,b1), acc[2j+1]=(b2,b3) for col j
__device__ __forceinline__ void mac8(ull* acc, ulonglong2 in, float4 w0, float4 w1) {
    fma2(acc[0],  in.x, dup2(w0.x)); fma2(acc[1],  in.y, dup2(w0.x));
    fma2(acc[2],  in.x, dup2(w0.y)); fma2(acc[3],  in.y, dup2(w0.y));
    fma2(acc[4],  in.x, dup2(w0.z)); fma2(acc[5],  in.y, dup2(w0.z));
    fma2(acc[6],  in.x, dup2(w0.w)); fma2(acc[7],  in.y, dup2(w0.w));
    fma2(acc[8],  in.x, dup2(w1.x)); fma2(acc[9],  in.y, dup2(w1.x));
    fma2(acc[10], in.x, dup2(w1.y)); fma2(acc[11], in.y, dup2(w1.y));
    fma2(acc[12], in.x, dup2(w1.z)); fma2(acc[13], in.y, dup2(w1.z));
    fma2(acc[14], in.x, dup2(w1.w)); fma2(acc[15], in.y, dup2(w1.w));
}

// 32 distinct rows per warp, 8-deep LDG prefetch.
__device__ __forceinline__ void gemm_rows32(ull* acc, const float* __restrict__ gp,
                                            const float* __restrict__ wp) {
    ulonglong2 ib[8];
    #pragma unroll
    for (int i = 0; i < 8; ++i)
        ib[i] = *reinterpret_cast<const ulonglong2*>(gp + (size_t)i*64);
    #pragma unroll
    for (int c = 0; c < 4; ++c) {
        #pragma unroll
        for (int i = 0; i < 8; ++i) {
            int r = c*8 + i;
            float4 w0 = *reinterpret_cast<const float4*>(wp + r*16);
            float4 w1 = *reinterpret_cast<const float4*>(wp + r*16 + 4);
            ulonglong2 in = ib[i];
            if (c < 3)
                ib[i] = *reinterpret_cast<const ulonglong2*>(gp + (size_t)(r+8)*64);
            mac8(acc, in, w0, w1);
        }
    }
}

__device__ __forceinline__ void gemm_rowsN(ull* acc, const float* __restrict__ gp,
                                           const float* __restrict__ wp, int n) {
    #pragma unroll 4
    for (int r = 0; r < n; ++r) {
        ulonglong2 in = *reinterpret_cast<const ulonglong2*>(gp + (size_t)r*64);
        float4 w0 = *reinterpret_cast<const float4*>(wp + r*16);
        float4 w1 = *reinterpret_cast<const float4*>(wp + r*16 + 4);
        mac8(acc, in, w0, w1);
    }
}

// sP layout: [slice 16][col 16][b 64]
__device__ __forceinline__ void store_partials(float* sP, int warp, int ch, int bg,
                                               const ull* acc) {
    float* pp = sP + warp*1024 + (ch*8)*64 + bg*4;
    #pragma unroll
    for (int j = 0; j < 8; ++j)
        *reinterpret_cast<ulonglong2*>(pp + j*64) = make_ulonglong2(acc[2*j], acc[2*j+1]);
}

__device__ __forceinline__ float reduce16(const float* sP, int col, int b) {
    const float* p = sP + col*64 + b;
    float s0 = p[0]       + p[1024];
    float s1 = p[2*1024]  + p[3*1024];
    float s2 = p[4*1024]  + p[5*1024];
    float s3 = p[6*1024]  + p[7*1024];
    s0 += p[8*1024]  + p[9*1024];
    s1 += p[10*1024] + p[11*1024];
    s2 += p[12*1024] + p[13*1024];
    s3 += p[14*1024] + p[15*1024];
    return (s0 + s1) + (s2 + s3);
}

// fast gates (~1e-6 rel err)
__device__ __forceinline__ float sigf2(float x) {
    return __fdividef(1.f, 1.f + __expf(-x));
}
__device__ __forceinline__ float tanhf2(float x) {
    return 1.f - __fdividef(2.f, __expf(2.f*x) + 1.f);
}

// ---------------- release/acquire barrier primitives ---------------------
__device__ __forceinline__ void bar_arrive(int slot) {
    asm volatile("red.release.gpu.global.add.u32 [%0], 1;"
                 :: "l"(g_barc + slot) : "memory");
}
__device__ __forceinline__ void bar_wait_ge(int slot, unsigned target) {
    unsigned v;
    do {
        asm volatile("ld.acquire.gpu.global.u32 %0, [%1];"
                     : "=r"(v) : "l"(g_barc + slot) : "memory");
    } while (v < target);
}

// ---------------- init: barrier vars + stroke transpose ------------------
__global__ void k_init(const float* __restrict__ strokes) {
    int i = blockIdx.x * blockDim.x + threadIdx.x;
    int stride = gridDim.x * blockDim.x;
    for (int j = i; j < Tn*3*Bn; j += stride) {
        int t = j / 192, rem = j % 192, dim = rem / 64, b = rem & 63;
        g_xT[j] = strokes[b*(Tn*3) + t*3 + dim];
    }
    if (i < 4) g_barc[i] = 0u;
}

// =========================================================================
// Layer-0 scan + attention.  128 CTAs x 512 thr persistent.
// warp w: h rows [32w,32w+32), w rows [512+4w,+4), warp15 adds x(3).
// slot0 = "h[t] ready" (S1), slot1 = "w[t] ready" (S2).
// Attention CTAs (0..63) cache Wd + trans[b] in SMEM; h[:,b] is staged into
// SMEM once per step (512 LDG) before the Wd matvec.
// =========================================================================
__global__ void __launch_bounds__(512, 1)
k_scan0(const float* __restrict__ trans,
        const float* __restrict__ W0, const float* __restrict__ R0,
        const float* __restrict__ b0, const float* __restrict__ Wd,
        const float* __restrict__ bd, float* __restrict__ attOut)
{
    extern __shared__ float sm[];
    float* sW  = sm;                        // 579*16  = 9264
    float* sP  = sm + 9264;                 // 16*16*64 = 16384
    float* sWd = sm + 9264 + 16384;         // 512*30 = 15360
    float* sTr = sm + 9264 + 16384 + 15360; // 64*64 = 4096
    float* sH  = sm + 9264 + 16384 + 15360 + 4096; // 512
    __shared__ float sb[16];
    __shared__ float sbd[30];
    __shared__ float sPart[16*32];
    __shared__ float sy[32];
    __shared__ float skap[10];
    __shared__ float swf[72];

    const int tid  = threadIdx.x;
    const int lane = tid & 31;
    const int warp = tid >> 5;
    const int bg   = lane & 15;
    const int ch   = lane >> 4;
    const int u0   = blockIdx.x * 4;
    const int bR   = tid & 63;
    const int uuR  = tid >> 6;
    const bool isAtt = (blockIdx.x < Bn);

    for (int idx = tid; idx < 9264; idx += 512) {
        int r = idx >> 4, c = idx & 15;
        int col = (c & 3) * 512 + u0 + (c >> 2);
        float v;
        if (r < 512)      v = R0[r*G4H + col];
        else if (r < 576) v = W0[(3 + r - 512)*G4H + col];
        else              v = W0[(r - 576)*G4H + col];
        sW[idx] = v;
    }
    if (isAtt) {
        for (int idx = tid; idx < 512*30; idx += 512) sWd[idx] = Wd[idx];
        const int b = blockIdx.x;
        for (int idx = tid; idx < 64*64; idx += 512)
            sTr[idx] = trans[b*(Un*Nn) + idx];
        if (tid < 30) sbd[tid] = bd[tid];
    }
    if (tid < 16) sb[tid] = b0[(tid & 3) * 512 + u0 + (tid >> 2)];
    if (tid < 10) skap[tid] = 0.f;
    __syncthreads();

    float creg = 0.f;

    for (int t = 0; t < Tn; ++t) {
        ull acc[16];
        #pragma unroll
        for (int i = 0; i < 16; ++i) acc[i] = 0ull;

        if (t > 0)
            gemm_rows32(acc, g_h0 + (size_t)(t-1)*HB + (warp*32)*64 + bg*4,
                        sW + (warp*32)*16 + ch*8);
        if (warp == 15)
            gemm_rowsN(acc, g_xT + (size_t)t*192 + bg*4, sW + 576*16 + ch*8, 3);
        // wait S2: w[t-1] ready
        if (tid == 0) bar_wait_ge(1, (unsigned)t * NCTA);
        __syncthreads();
        if (t > 0)
            gemm_rowsN(acc, g_w + (size_t)(t-1)*NB + (warp*4)*64 + bg*4,
                       sW + (512 + warp*4)*16 + ch*8, 4);

        store_partials(sP, warp, ch, bg, acc);
        __syncthreads();
        if (tid < 256) {
            float z[4];
            #pragma unroll
            for (int g = 0; g < 4; ++g)
                z[g] = sb[uuR*4 + g] + reduce16(sP, uuR*4 + g, bR);
            float c2 = sigf2(z[1])*creg + sigf2(z[0])*tanhf2(z[2]);
            creg = c2;
            g_h0[(size_t)t*HB + (u0+uuR)*64 + bR] = sigf2(z[3])*tanhf2(c2);
        }
        // S1: h[t] ready everywhere
        __syncthreads();
        if (tid == 0) { bar_arrive(0); bar_wait_ge(0, (unsigned)(t+1) * NCTA); }
        __syncthreads();

        // attention on CTAs 0..63
        if (isAtt) {
            const int b = blockIdx.x;
            // stage h[t][:,b] into SMEM: 512 independent LDG (full MLP)
            sH[tid] = g_h0[(size_t)t*HB + tid*64 + b];
            __syncthreads();

            // Wd matvec from SMEM (h broadcast, Wd conflict-free)
            int cc = tid & 31, seg = tid >> 5;
            if (cc < 30) {
                int dbase = seg * 32;
                float part = 0.f;
                #pragma unroll 8
                for (int d = 0; d < 32; ++d)
                    part += sH[dbase + d] * sWd[(dbase + d)*30 + cc];
                sPart[seg*32 + cc] = part;
            }
            __syncthreads();

            // exp chain entirely in warp 0
            if (warp == 0) {
                if (lane < 30) {
                    float y = sbd[lane];
                    #pragma unroll
                    for (int s = 0; s < 16; ++s) y += sPart[s*32 + lane];
                    sy[lane] = expf(y);
                }
                __syncwarp();
                if (lane < Kn) skap[lane] += sy[20 + lane];
                __syncwarp();
            }
            __syncthreads();

            if (tid < Un + 1) {
                float s = 0.f;
                #pragma unroll
                for (int k = 0; k < Kn; ++k) {
                    float dd  = skap[k] - (float)(tid + 1);
                    float arg = -sy[10 + k] * dd * dd;
                    if (arg < EXP_LO) arg = EXP_LO;   // Eigen pexp clamp
                    s += sy[k] * expf(arg);
                }
                swf[tid] = s;
            }
            __syncthreads();

            // w2 on threads 0..63; argmax concurrently on thread 64
            if (tid < Nn) {
                float acc2 = 0.f;
                #pragma unroll 8
                for (int u = 0; u < Un; ++u)
                    acc2 += swf[u] * sTr[u*64 + tid];
                g_w[(size_t)t*NB + tid*64 + b] = acc2;
            } else if (tid == 64) {
                float best = swf[0]; int bi = 0;
                #pragma unroll 8
                for (int u = 1; u < Un + 1; ++u)
                    if (swf[u] > best) { best = swf[u]; bi = u; }
                attOut[b*Tn + t] = (float)bi;
            }
            __syncthreads();
            if (tid == 0) bar_arrive(1);   // S2: w[t] done
        } else {
            if (tid == 0) bar_arrive(1);
        }
    }
}

// =========================================================================
// Fused layers 1/2 scan: z = [h_in, w, x]@Wff + h[t-1]@R + b ; LSTM.
// Feedforward GEMM of step t+1 runs between barrier arrive and wait.
// =========================================================================
__global__ void __launch_bounds__(512, 1)
k_scan12f(const float* __restrict__ R, const float* __restrict__ W,
          const float* __restrict__ bias, int sel)
{
    extern __shared__ float sm[];
    float* sW = sm;                  // 1091*16 = 17456
    float* sP = sm + 17456;          // 16384
    __shared__ float sb[16];

    const float* hin = (sel == 1) ? g_h0 : g_h1;
    float* hseq      = (sel == 1) ? g_h1 : g_h2;
    const int slot = sel + 1;        // 2 or 3
    const int tid  = threadIdx.x;
    const int lane = tid & 31;
    const int warp = tid >> 5;
    const int bg   = lane & 15;
    const int ch   = lane >> 4;
    const int u0   = blockIdx.x * 4;
    const int bR   = tid & 63;
    const int uuR  = tid >> 6;

    for (int idx = tid; idx < 1091*16; idx += 512) {
        int r = idx >> 4, c = idx & 15;
        int col = (c & 3) * 512 + u0 + (c >> 2);
        float v;
        if (r < 512)       v = R[r*G4H + col];
        else if (r < 1024) v = W[(r - 512)*G4H + col];
        else if (r < 1088) v = W[(512 + r - 1024)*G4H + col];
        else               v = W[(576 + r - 1088)*G4H + col];
        sW[idx] = v;
    }
    if (tid < 16) sb[tid] = bias[(tid & 3) * 512 + u0 + (tid >> 2)];
    float creg = 0.f;
    __syncthreads();

    ull acc[16];
    #pragma unroll
    for (int i = 0; i < 16; ++i) acc[i] = 0ull;
    gemm_rows32(acc, hin + (size_t)0*HB + (warp*32)*64 + bg*4,
                sW + (512 + warp*32)*16 + ch*8);
    gemm_rowsN(acc, g_w + (size_t)0*NB + (warp*4)*64 + bg*4,
               sW + (1024 + warp*4)*16 + ch*8, 4);
    if (warp == 15)
        gemm_rowsN(acc, g_xT + (size_t)0*192 + bg*4, sW + 1088*16 + ch*8, 3);

    for (int t = 0; t < Tn; ++t) {
        if (t > 0)
            gemm_rows32(acc, hseq + (size_t)(t-1)*HB + (warp*32)*64 + bg*4,
                        sW + (warp*32)*16 + ch*8);

        store_partials(sP, warp, ch, bg, acc);
        __syncthreads();
        if (tid < 256) {
            float z[4];
            #pragma unroll
            for (int g = 0; g < 4; ++g)
                z[g] = sb[uuR*4 + g] + reduce16(sP, uuR*4 + g, bR);
            float c2 = sigf2(z[1])*creg + sigf2(z[0])*tanhf2(z[2]);
            creg = c2;
            hseq[(size_t)t*HB + (u0+uuR)*64 + bR] = sigf2(z[3])*tanhf2(c2);
        }
        __syncthreads();
        if (tid == 0) bar_arrive(slot);

        #pragma unroll
        for (int i = 0; i < 16; ++i) acc[i] = 0ull;
        if (t < Tn - 1) {
            gemm_rows32(acc, hin + (size_t)(t+1)*HB + (warp*32)*64 + bg*4,
                        sW + (512 + warp*32)*16 + ch*8);
            gemm_rowsN(acc, g_w + (size_t)(t+1)*NB + (warp*4)*64 + bg*4,
                       sW + (1024 + warp*4)*16 + ch*8, 4);
            if (warp == 15)
                gemm_rowsN(acc, g_xT + (size_t)(t+1)*192 + bg*4,
                           sW + 1088*16 + ch*8, 3);
        }
        if (tid == 0) bar_wait_ge(slot, (unsigned)(t+1) * NCTA);
        __syncthreads();
    }
}

// =========================================================================
// Output GEMM: out[b][t][o] = [h0,h1,h2][t] @ Wo + bo   (grid = 800 CTAs)
// =========================================================================
__global__ void __launch_bounds__(256)
k_out(const float* __restrict__ Wo, const float* __restrict__ bo,
      float* __restrict__ out)
{
    const int t = blockIdx.x;
    const int tid = threadIdx.x;
    const int c = tid & 127;
    const int bh = tid >> 7;
    if (c >= On) return;

    ull acc[16];
    ull bias2 = dup2(bo[c]);
    #pragma unroll
    for (int i = 0; i < 16; ++i) acc[i] = bias2;

    #pragma unroll
    for (int l = 0; l < 3; ++l) {
        const float* hp = (l == 0 ? g_h0 : l == 1 ? g_h1 : g_h2) + (size_t)t*HB;
        const float* wp = Wo + (l*512)*On + c;
        #pragma unroll 2
        for (int d = 0; d < 512; ++d) {
            ull wv = dup2(wp[d*On]);
            const ulonglong2* h4 = reinterpret_cast<const ulonglong2*>(hp + d*64 + bh*32);
            #pragma unroll
            for (int q = 0; q < 8; ++q) {
                ulonglong2 hv = h4[q];
                fma2(acc[2*q],   hv.x, wv);
                fma2(acc[2*q+1], hv.y, wv);
            }
        }
    }
    #pragma unroll
    for (int i = 0; i < 16; ++i) {
        float lo, hi; unpack2(acc[i], lo, hi);
        int b = bh*32 + 2*i;
        out[(size_t)b     *(Tn*On) + t*On + c] = lo;
        out[(size_t)(b+1) *(Tn*On) + t*On + c] = hi;
    }
}

// =========================================================================
extern "C" void kernel_launch(void* const* d_in, const int* in_sizes, int n_in,
                              void* d_out, int out_size)
{
    const float* strokes = (const float*)d_in[0];
    const float* trans   = (const float*)d_in[1];
    const float* W0      = (const float*)d_in[2];
    const float* R0      = (const float*)d_in[3];
    const float* b0      = (const float*)d_in[4];
    const float* Wd      = (const float*)d_in[5];
    const float* bd      = (const float*)d_in[6];
    const float* W1      = (const float*)d_in[7];
    const float* R1      = (const float*)d_in[8];
    const float* b1      = (const float*)d_in[9];
    const float* W2      = (const float*)d_in[10];
    const float* R2      = (const float*)d_in[11];
    const float* b2      = (const float*)d_in[12];
    const float* Wo      = (const float*)d_in[13];
    const float* bo      = (const float*)d_in[14];

    float* out = (float*)d_out;
    float* att = out + (size_t)Bn * Tn * On;

    const int smem_scan0 = (9264 + 16384 + 15360 + 4096 + 512) * 4;  // 182464
    const int smem_s12f  = (17456 + 16384) * 4;                      // 135360
    cudaFuncSetAttribute(k_scan0,   cudaFuncAttributeMaxDynamicSharedMemorySize, smem_scan0);
    cudaFuncSetAttribute(k_scan12f, cudaFuncAttributeMaxDynamicSharedMemorySize, smem_s12f);

    k_init<<<256, 256>>>(strokes);
    k_scan0<<<NCTA, 512, smem_scan0>>>(trans, W0, R0, b0, Wd, bd, att);
    k_scan12f<<<NCTA, 512, smem_s12f>>>(R1, W1, b1, 1);
    k_scan12f<<<NCTA, 512, smem_s12f>>>(R2, W2, b2, 2);
    k_out<<<Tn, 256>>>(Wo, bo, out);
}